// round 12
// baseline (speedup 1.0000x reference)
#include <cuda_runtime.h>
#include <cuda_bf16.h>
#include <cstdint>

// Problem constants
#define NNODES 100000
#define DIM    256
#define NBASES 8
#define NRELS  16
#define NEDGES 800000
#define HCOLS  128          // columns per pass (DIM/2)

// ---------------------------------------------------------------------------
// Static device scratch (~535 MB; half-size msg buffer, two-pass)
// ---------------------------------------------------------------------------
__device__ float         g_msg[(size_t)NEDGES * HCOLS];      // 409.6 MB per-pass messages
__device__ __nv_bfloat16 g_Ah[(size_t)NNODES * DIM];         // 51.2 MB hi(emb[node_ids])
__device__ __nv_bfloat16 g_Al[(size_t)NNODES * DIM];         // 51.2 MB lo residual
__device__ __nv_bfloat16 g_Wth[(size_t)NRELS * DIM * DIM];   // 2 MB hi(W[r]^T) [r][n][k]
__device__ __nv_bfloat16 g_Wtl[(size_t)NRELS * DIM * DIM];   // 2 MB lo residual
__device__ int g_dcnt[NNODES];        // in-degree (dst histogram)
__device__ int g_dstart[NNODES];      // dst CSR starts
__device__ int g_dcur[NNODES];        // dst fill cursors
__device__ int g_dperm[NEDGES];       // message-row ids sorted by dst
__device__ int g_cnt16[NRELS];        // relation histogram
__device__ int g_start16[NRELS];      // bucket starts (exclusive scan)
__device__ int g_cur16[NRELS];        // fill cursors
__device__ int g_pstart[NRELS + 1];   // padded bucket starts (multiples of 128)
__device__ int g_perm[NEDGES];        // edge ids sorted by relation

// ---------------------------------------------------------------------------
// PTX helpers (compute_100-safe: ldmatrix + mma.sync + cp.async, NO tcgen05)
// ---------------------------------------------------------------------------
__device__ __forceinline__ uint32_t smem_to_u32(const void* p) {
    uint32_t a;
    asm("{ .reg .u64 t; cvta.to.shared.u64 t, %1; cvt.u32.u64 %0, t; }" : "=r"(a) : "l"(p));
    return a;
}
__device__ __forceinline__ void ldsm_x4(uint32_t& r0, uint32_t& r1, uint32_t& r2,
                                        uint32_t& r3, uint32_t addr) {
    asm volatile("ldmatrix.sync.aligned.m8n8.x4.shared.b16 {%0,%1,%2,%3}, [%4];"
                 : "=r"(r0), "=r"(r1), "=r"(r2), "=r"(r3) : "r"(addr));
}
__device__ __forceinline__ void mma_bf16(float* c, const uint32_t* a, const uint32_t* b) {
    asm volatile("mma.sync.aligned.m16n8k16.row.col.f32.bf16.bf16.f32 "
                 "{%0,%1,%2,%3}, {%4,%5,%6,%7}, {%8,%9}, {%0,%1,%2,%3};"
                 : "+f"(c[0]), "+f"(c[1]), "+f"(c[2]), "+f"(c[3])
                 : "r"(a[0]), "r"(a[1]), "r"(a[2]), "r"(a[3]), "r"(b[0]), "r"(b[1]));
}
__device__ __forceinline__ void cp_async16(uint32_t saddr, const void* gptr) {
    asm volatile("cp.async.cg.shared.global [%0], [%1], 16;"
                 :: "r"(saddr), "l"(gptr) : "memory");
}
#define CP_COMMIT() asm volatile("cp.async.commit_group;" ::: "memory")
#define CP_WAIT(n)  asm volatile("cp.async.wait_group %0;" :: "n"(n) : "memory")

// ---------------------------------------------------------------------------
// K0: zero histograms (out is written exactly once by the reduce passes)
// ---------------------------------------------------------------------------
__global__ void zero_kernel() {
    int i = blockIdx.x * blockDim.x + threadIdx.x;
    if (i < NNODES) g_dcnt[i] = 0;
    if (i < NRELS) g_cnt16[i] = 0;
}

// ---------------------------------------------------------------------------
// K1: split A = emb[node_ids] into hi/lo bf16
// ---------------------------------------------------------------------------
__global__ __launch_bounds__(256)
void split_a_kernel(const float* __restrict__ emb, const int* __restrict__ node_ids) {
    size_t t = (size_t)blockIdx.x * blockDim.x + threadIdx.x;  // over N*D/4
    const size_t tot = (size_t)NNODES * (DIM / 4);
    if (t >= tot) return;
    int row = (int)(t >> 6);
    int c4  = (int)(t & 63);
    int nid = node_ids[row];
    float4 v = ((const float4*)(emb + (size_t)nid * DIM))[c4];
    __nv_bfloat16 hx = __float2bfloat16(v.x), hy = __float2bfloat16(v.y);
    __nv_bfloat16 hz = __float2bfloat16(v.z), hw = __float2bfloat16(v.w);
    __nv_bfloat16 lx = __float2bfloat16(v.x - __bfloat162float(hx));
    __nv_bfloat16 ly = __float2bfloat16(v.y - __bfloat162float(hy));
    __nv_bfloat16 lz = __float2bfloat16(v.z - __bfloat162float(hz));
    __nv_bfloat16 lw = __float2bfloat16(v.w - __bfloat162float(hw));
    __nv_bfloat162* ph = (__nv_bfloat162*)g_Ah;
    __nv_bfloat162* pl = (__nv_bfloat162*)g_Al;
    ph[t * 2]     = __nv_bfloat162{hx, hy};
    ph[t * 2 + 1] = __nv_bfloat162{hz, hw};
    pl[t * 2]     = __nv_bfloat162{lx, ly};
    pl[t * 2 + 1] = __nv_bfloat162{lz, lw};
}

// ---------------------------------------------------------------------------
// K2: build W^T[r][n][k] = sum_b w_comp[r,b] * basis[b][k][n], split hi/lo
// ---------------------------------------------------------------------------
__global__ __launch_bounds__(256)
void build_w_kernel(const float* __restrict__ basis, const float* __restrict__ w_comp) {
    __shared__ float wc[NRELS * NBASES];
    if (threadIdx.x < NRELS * NBASES) wc[threadIdx.x] = w_comp[threadIdx.x];
    __syncthreads();
    int idx = blockIdx.x * blockDim.x + threadIdx.x;   // 65536 = (n,k)
    if (idx >= DIM * DIM) return;
    int n = idx >> 8;
    int k = idx & 255;
    float bv[NBASES];
    #pragma unroll
    for (int b = 0; b < NBASES; b++)
        bv[b] = __ldg(basis + (size_t)b * DIM * DIM + (size_t)k * DIM + n);
    #pragma unroll
    for (int r = 0; r < NRELS; r++) {
        float x = 0.f;
        #pragma unroll
        for (int b = 0; b < NBASES; b++) x = fmaf(wc[r * NBASES + b], bv[b], x);
        __nv_bfloat16 h = __float2bfloat16(x);
        __nv_bfloat16 l = __float2bfloat16(x - __bfloat162float(h));
        g_Wth[(size_t)r * DIM * DIM + idx] = h;
        g_Wtl[(size_t)r * DIM * DIM + idx] = l;
    }
}

// ---------------------------------------------------------------------------
// K3: histograms (etype bucket counts smem-aggregated; dst in-degree direct)
// ---------------------------------------------------------------------------
__global__ __launch_bounds__(256)
void ehist_kernel(const int* __restrict__ et, const int* __restrict__ dst) {
    __shared__ int h[NRELS];
    if (threadIdx.x < NRELS) h[threadIdx.x] = 0;
    __syncthreads();
    int e = blockIdx.x * blockDim.x + threadIdx.x;
    if (e < NEDGES) {
        atomicAdd(&h[et[e]], 1);
        atomicAdd(&g_dcnt[dst[e]], 1);
    }
    __syncthreads();
    if (threadIdx.x < NRELS) atomicAdd(&g_cnt16[threadIdx.x], h[threadIdx.x]);
}

// ---------------------------------------------------------------------------
// K4: tiny scan over 16 buckets (1 warp)
// ---------------------------------------------------------------------------
__global__ void scan16_kernel() {
    int lane = threadIdx.x;
    int c = (lane < NRELS) ? g_cnt16[lane] : 0;
    int p = (lane < NRELS) ? ((c + 127) & ~127) : 0;
    int xc = c, xp = p;
    #pragma unroll
    for (int d = 1; d < 32; d <<= 1) {
        int yc = __shfl_up_sync(0xffffffffu, xc, d);
        int yp = __shfl_up_sync(0xffffffffu, xp, d);
        if (lane >= d) { xc += yc; xp += yp; }
    }
    if (lane < NRELS) {
        g_start16[lane] = xc - c;
        g_cur16[lane]   = xc - c;
        g_pstart[lane]  = xp - p;
    }
    if (lane == NRELS) g_pstart[NRELS] = xp;   // inclusive total of padded counts
}

// ---------------------------------------------------------------------------
// K5: fill relation permutation (block-ranked counting sort)
// ---------------------------------------------------------------------------
__global__ __launch_bounds__(256)
void fill_kernel(const int* __restrict__ et) {
    __shared__ int h[NRELS], base[NRELS];
    if (threadIdx.x < NRELS) h[threadIdx.x] = 0;
    __syncthreads();
    int e = blockIdx.x * blockDim.x + threadIdx.x;
    int r = 0, rank = 0;
    if (e < NEDGES) {
        r = et[e];
        rank = atomicAdd(&h[r], 1);
    }
    __syncthreads();
    if (threadIdx.x < NRELS)
        base[threadIdx.x] = atomicAdd(&g_cur16[threadIdx.x], h[threadIdx.x]);
    __syncthreads();
    if (e < NEDGES) g_perm[base[r] + rank] = e;
}

// ---------------------------------------------------------------------------
// K5b: exclusive scan of g_dcnt -> g_dstart, g_dcur (single block)
// ---------------------------------------------------------------------------
__global__ __launch_bounds__(1024)
void dscan_kernel() {
    __shared__ int warp_sums[32];
    __shared__ int s_carry;
    int tid = threadIdx.x, lane = tid & 31, wid = tid >> 5;
    if (tid == 0) s_carry = 0;
    __syncthreads();
    for (int base = 0; base < NNODES; base += 1024) {
        int i = base + tid;
        int v = (i < NNODES) ? g_dcnt[i] : 0;
        int x = v;
        #pragma unroll
        for (int d = 1; d < 32; d <<= 1) {
            int y = __shfl_up_sync(0xffffffffu, x, d);
            if (lane >= d) x += y;
        }
        if (lane == 31) warp_sums[wid] = x;
        __syncthreads();
        if (wid == 0) {
            int s = warp_sums[lane];
            #pragma unroll
            for (int d = 1; d < 32; d <<= 1) {
                int y = __shfl_up_sync(0xffffffffu, s, d);
                if (lane >= d) s += y;
            }
            warp_sums[lane] = s;
        }
        __syncthreads();
        int woff = (wid > 0) ? warp_sums[wid - 1] : 0;
        int excl = x + woff - v + s_carry;
        if (i < NNODES) { g_dstart[i] = excl; g_dcur[i] = excl; }
        int block_total = warp_sums[31];
        __syncthreads();
        if (tid == 0) s_carry += block_total;
        __syncthreads();
    }
}

// ---------------------------------------------------------------------------
// K5c: fill dst permutation over message-row ids.
//  Message row of edge = its (unpadded) position p in the relation perm.
// ---------------------------------------------------------------------------
__global__ __launch_bounds__(256)
void dfill_kernel(const int* __restrict__ dst) {
    int p = blockIdx.x * blockDim.x + threadIdx.x;
    if (p >= NEDGES) return;
    int e = g_perm[p];
    int d = __ldg(dst + e);
    int pos = atomicAdd(&g_dcur[d], 1);
    g_dperm[pos] = p;
}

// ---------------------------------------------------------------------------
// K6: PERSISTENT GEMM for ONE n-half; messages written with PLAIN stores.
//  g_msg[p][0:128] = norm_e * (x[src_e] @ W[r])[:, n0h*128 : +128]
//  B operand (W^T half, 132 KB) resident per relation; A streams in cp.async
//  double-buffered 32 KB chunks.
// ---------------------------------------------------------------------------
#define A_PAD      72
#define A_SPLIT_B  (128 * A_PAD * 2)        // 18432 B per split
#define A_STAGE_B  (2 * A_SPLIT_B)          // 36864 B per stage
#define B_PAD      264
#define B_SPLIT_B  (128 * B_PAD * 2)        // 67584 B per split
#define SM_B_OFF   (2 * A_STAGE_B)          // 73728
#define SM_META_OFF (SM_B_OFF + 2 * B_SPLIT_B)   // 208896
#define SM_TOTAL   (SM_META_OFF + 1536)     // 210432 bytes
#define NCTA_PERSIST 148

__global__ __launch_bounds__(256)
void gemm_persist_kernel(const int* __restrict__ src,
                         const float* __restrict__ norm,
                         int n0h) {
    extern __shared__ char smem[];
    int*   s_src  = (int*)(smem + SM_META_OFF);
    int*   s_midx = (int*)(smem + SM_META_OFF + 512);
    float* s_norm = (float*)(smem + SM_META_OFF + 1024);
    const uint32_t smAu = smem_to_u32(smem);
    const uint32_t smBu = smAu + SM_B_OFF;

    const int tid  = threadIdx.x;
    const int lane = tid & 31;
    const int w    = tid >> 5;
    const int mw   = w >> 1;        // 0..3
    const int nw   = w & 1;         // 0..1

    const int T = g_pstart[NRELS] >> 7;          // total 128-row blocks
    const int t_begin = (int)((long long)T * blockIdx.x / gridDim.x);
    const int t_end   = (int)((long long)T * (blockIdx.x + 1) / gridDim.x);

    int cur_key = -1;

    for (int t = t_begin; t < t_end; t++) {
        // ---- decode tile -> (r, blk) from g_pstart ----
        int r = 0;
        #pragma unroll
        for (int i = 1; i < NRELS; i++)
            if (t >= (g_pstart[i] >> 7)) r = i;
        const int blk = t - (g_pstart[r] >> 7);

        __syncthreads();   // all warps past previous tile's smem reads

        // ---- B residency: reload only when relation changes ----
        if (r != cur_key) {
            cur_key = r;
            const __nv_bfloat16* Wh = g_Wth + (size_t)r * DIM * DIM + (size_t)n0h * 128 * DIM;
            const __nv_bfloat16* Wl = g_Wtl + (size_t)r * DIM * DIM + (size_t)n0h * 128 * DIM;
            #pragma unroll
            for (int it = 0; it < 32; it++) {
                int i = it * 256 + tid;           // 0..8191
                int split = i >> 12;
                int rem = i & 4095;
                int nrow = rem >> 5;
                int kg = (rem & 31) * 8;          // element offset
                const __nv_bfloat16* gp = (split ? Wl : Wh) + (size_t)nrow * DIM + kg;
                cp_async16(smBu + split * B_SPLIT_B + nrow * (B_PAD * 2) + kg * 2, gp);
            }
            CP_COMMIT();
            CP_WAIT(0);
        }

        // ---- edge metadata ----
        if (tid < 128) {
            int local_e = blk * 128 + tid;
            bool ok = (local_e < g_cnt16[r]);
            int p = g_start16[r] + local_e;
            int e = ok ? g_perm[p] : -1;
            s_src[tid]  = (e >= 0) ? __ldg(src + e) : 0;
            s_midx[tid] = ok ? p : -1;
            s_norm[tid] = (e >= 0) ? __ldg(norm + e) : 0.f;
        }
        __syncthreads();

        #define A_ISSUE(KC, ST) do {                                              \
            int kbase_ = (KC) * 64;                                                \
            _Pragma("unroll")                                                      \
            for (int it_ = 0; it_ < 8; it_++) {                                    \
                int i_ = it_ * 256 + tid;                                          \
                int split_ = i_ >> 10;                                             \
                int rem_ = i_ & 1023;                                              \
                int row_ = rem_ >> 3;                                              \
                int kg_ = (rem_ & 7) * 8;                                          \
                const __nv_bfloat16* ga_ = split_ ? g_Al : g_Ah;                   \
                const __nv_bfloat16* gp_ = ga_ + (size_t)s_src[row_] * DIM + kbase_ + kg_; \
                cp_async16(smAu + (ST) * A_STAGE_B + split_ * A_SPLIT_B +          \
                           (row_ * A_PAD + kg_) * 2, gp_);                         \
            }                                                                      \
            CP_COMMIT();                                                           \
        } while (0)

        A_ISSUE(0, 0);

        float acc[2][8][4];
        #pragma unroll
        for (int i = 0; i < 2; i++)
            #pragma unroll
            for (int j = 0; j < 8; j++)
                #pragma unroll
                for (int k = 0; k < 4; k++) acc[i][j][k] = 0.f;

        for (int kc = 0; kc < 4; kc++) {
            if (kc < 3) {
                if (kc == 0)      A_ISSUE(1, 1);
                else if (kc == 1) A_ISSUE(2, 0);
                else              A_ISSUE(3, 1);
                CP_WAIT(1);
            } else {
                CP_WAIT(0);
            }
            __syncthreads();

            const uint32_t sA = smAu + (kc & 1) * A_STAGE_B;
            #pragma unroll
            for (int kk = 0; kk < 4; kk++) {
                const int kof = kk * 16 + ((lane >> 4) << 3);
                uint32_t ah[2][4], al[2][4];
                #pragma unroll
                for (int mi = 0; mi < 2; mi++) {
                    int row = mw * 32 + mi * 16 + (lane & 15);
                    uint32_t adr = sA + (uint32_t)(row * A_PAD + kof) * 2;
                    ldsm_x4(ah[mi][0], ah[mi][1], ah[mi][2], ah[mi][3], adr);
                    ldsm_x4(al[mi][0], al[mi][1], al[mi][2], al[mi][3],
                            adr + A_SPLIT_B);
                }
                const int kof_b = kc * 64 + kk * 16 + (((lane >> 3) & 1) << 3);
                #pragma unroll
                for (int nt2 = 0; nt2 < 4; nt2++) {
                    int nrow = nw * 64 + (nt2 * 2 + ((lane >> 4) & 1)) * 8 + (lane & 7);
                    uint32_t adr = smBu + (uint32_t)(nrow * B_PAD + kof_b) * 2;
                    uint32_t bh[4], bl[4];
                    ldsm_x4(bh[0], bh[1], bh[2], bh[3], adr);
                    ldsm_x4(bl[0], bl[1], bl[2], bl[3], adr + B_SPLIT_B);
                    #pragma unroll
                    for (int p = 0; p < 2; p++) {
                        int nt = nt2 * 2 + p;
                        #pragma unroll
                        for (int mi = 0; mi < 2; mi++) {
                            mma_bf16(acc[mi][nt], ah[mi], &bh[2 * p]);
                            mma_bf16(acc[mi][nt], al[mi], &bh[2 * p]);
                            mma_bf16(acc[mi][nt], ah[mi], &bl[2 * p]);
                        }
                    }
                }
            }
            __syncthreads();   // stage consumed before it is refilled
        }
        #undef A_ISSUE

        // ---- epilogue: plain float2 stores into half-width msg rows ----
        const int qrow = lane >> 2;
        const int qcol = (lane & 3) * 2;
        const int colbase = nw * 64;
        #pragma unroll
        for (int mi = 0; mi < 2; mi++) {
            int lr0 = mw * 32 + mi * 16 + qrow;
            int lr1 = lr0 + 8;
            int m0 = s_midx[lr0], m1 = s_midx[lr1];
            float nm0 = s_norm[lr0], nm1 = s_norm[lr1];
            float* o0 = g_msg + (size_t)m0 * HCOLS + colbase;
            float* o1 = g_msg + (size_t)m1 * HCOLS + colbase;
            #pragma unroll
            for (int nt = 0; nt < 8; nt++) {
                float* c = acc[mi][nt];
                int col = nt * 8 + qcol;
                if (m0 >= 0) *(float2*)(o0 + col) = make_float2(c[0] * nm0, c[1] * nm0);
                if (m1 >= 0) *(float2*)(o1 + col) = make_float2(c[2] * nm1, c[3] * nm1);
            }
        }
    }
}

// ---------------------------------------------------------------------------
// K7: gather-reduce for one n-half.  One warp per dst node: sum its message
//  rows (float4 per lane, 4-wide MLP), divide by in-degree, add bias, write
//  out[d][h*128 : +128] once.  Absorbs zero(out) + finalize.
// ---------------------------------------------------------------------------
__global__ __launch_bounds__(256)
void reduce_kernel(const float* __restrict__ bias, float* __restrict__ out, int h) {
    int d = (int)(((size_t)blockIdx.x * blockDim.x + threadIdx.x) >> 5);
    int lane = threadIdx.x & 31;
    if (d >= NNODES) return;

    int p   = g_dstart[d];
    int cnt = g_dcnt[d];
    int end = p + cnt;

    float4 a = make_float4(0.f, 0.f, 0.f, 0.f);

    for (; p + 3 < end; p += 4) {
        int r0 = __ldg(g_dperm + p);
        int r1 = __ldg(g_dperm + p + 1);
        int r2 = __ldg(g_dperm + p + 2);
        int r3 = __ldg(g_dperm + p + 3);
        float4 v0 = __ldg((const float4*)(g_msg + (size_t)r0 * HCOLS) + lane);
        float4 v1 = __ldg((const float4*)(g_msg + (size_t)r1 * HCOLS) + lane);
        float4 v2 = __ldg((const float4*)(g_msg + (size_t)r2 * HCOLS) + lane);
        float4 v3 = __ldg((const float4*)(g_msg + (size_t)r3 * HCOLS) + lane);
        a.x += (v0.x + v1.x) + (v2.x + v3.x);
        a.y += (v0.y + v1.y) + (v2.y + v3.y);
        a.z += (v0.z + v1.z) + (v2.z + v3.z);
        a.w += (v0.w + v1.w) + (v2.w + v3.w);
    }
    for (; p < end; p++) {
        int r0 = __ldg(g_dperm + p);
        float4 v0 = __ldg((const float4*)(g_msg + (size_t)r0 * HCOLS) + lane);
        a.x += v0.x; a.y += v0.y; a.z += v0.z; a.w += v0.w;
    }

    float inv = (cnt > 0) ? (1.0f / (float)cnt) : 0.0f;
    float4 b = __ldg((const float4*)bias + h * 32 + lane);
    float4 o;
    o.x = fmaf(a.x, inv, b.x);
    o.y = fmaf(a.y, inv, b.y);
    o.z = fmaf(a.z, inv, b.z);
    o.w = fmaf(a.w, inv, b.w);

    ((float4*)(out + (size_t)d * DIM + h * HCOLS))[lane] = o;
}

// ---------------------------------------------------------------------------
// kernel_launch
// Inputs (metadata order): node_ids[i32,N], src[i32,E], dst[i32,E],
//   etypes[i32,E], norm[f32,E], emb[f32,N*D], basis[f32,B*D*D],
//   w_comp[f32,R*B], h_bias[f32,D].  Output: f32 [N, D].
// ---------------------------------------------------------------------------
extern "C" void kernel_launch(void* const* d_in, const int* in_sizes, int n_in,
                              void* d_out, int out_size) {
    const int*   node_ids = (const int*)  d_in[0];
    const int*   src      = (const int*)  d_in[1];
    const int*   dst      = (const int*)  d_in[2];
    const int*   etypes   = (const int*)  d_in[3];
    const float* norm     = (const float*)d_in[4];
    const float* emb      = (const float*)d_in[5];
    const float* basis    = (const float*)d_in[6];
    const float* w_comp   = (const float*)d_in[7];
    const float* h_bias   = (const float*)d_in[8];
    float* out = (float*)d_out;

    const int tot4 = NNODES * DIM / 4;
    const int blk4 = (tot4 + 255) / 256;

    cudaFuncSetAttribute(gemm_persist_kernel,
                         cudaFuncAttributeMaxDynamicSharedMemorySize, SM_TOTAL);

    zero_kernel<<<(NNODES + 255) / 256, 256>>>();
    split_a_kernel<<<blk4, 256>>>(emb, node_ids);
    build_w_kernel<<<(DIM * DIM + 255) / 256, 256>>>(basis, w_comp);

    ehist_kernel<<<(NEDGES + 255) / 256, 256>>>(etypes, dst);
    scan16_kernel<<<1, 32>>>();
    fill_kernel<<<(NEDGES + 255) / 256, 256>>>(etypes);
    dscan_kernel<<<1, 1024>>>();
    dfill_kernel<<<(NEDGES + 255) / 256, 256>>>(dst);

    // Two passes over n-halves: GEMM -> reduce, msg buffer reused.
    gemm_persist_kernel<<<NCTA_PERSIST, 256, SM_TOTAL>>>(src, norm, 0);
    reduce_kernel<<<(NNODES * 32 + 255) / 256, 256>>>(h_bias, out, 0);
    gemm_persist_kernel<<<NCTA_PERSIST, 256, SM_TOTAL>>>(src, norm, 1);
    reduce_kernel<<<(NNODES * 32 + 255) / 256, 256>>>(h_bias, out, 1);
}

// round 13
// speedup vs baseline: 1.0675x; 1.0675x over previous
#include <cuda_runtime.h>
#include <cuda_bf16.h>
#include <cstdint>

// Problem constants
#define NNODES 100000
#define DIM    256
#define NBASES 8
#define NRELS  16
#define NEDGES 800000

// ---------------------------------------------------------------------------
// Static device scratch (~105 MB)
// ---------------------------------------------------------------------------
__device__ __nv_bfloat16 g_Ah[(size_t)NNODES * DIM];         // 51.2 MB hi(emb[node_ids])
__device__ __nv_bfloat16 g_Al[(size_t)NNODES * DIM];         // 51.2 MB lo residual
__device__ __nv_bfloat16 g_Wth[(size_t)NRELS * DIM * DIM];   // 2 MB hi(W[r]^T) [r][n][k]
__device__ __nv_bfloat16 g_Wtl[(size_t)NRELS * DIM * DIM];   // 2 MB lo residual
__device__ int g_dcnt[NNODES];        // in-degree (dst histogram)
__device__ int g_cnt16[NRELS];        // relation histogram
__device__ int g_start16[NRELS];      // bucket starts (exclusive scan)
__device__ int g_cur16[NRELS];        // fill cursors
__device__ int g_pstart[NRELS + 1];   // padded bucket starts (multiples of 128)
__device__ int g_perm[NEDGES];        // edge ids sorted by relation

// ---------------------------------------------------------------------------
// PTX helpers (compute_100-safe: ldmatrix + mma.sync + cp.async, NO tcgen05)
// ---------------------------------------------------------------------------
__device__ __forceinline__ uint32_t smem_to_u32(const void* p) {
    uint32_t a;
    asm("{ .reg .u64 t; cvta.to.shared.u64 t, %1; cvt.u32.u64 %0, t; }" : "=r"(a) : "l"(p));
    return a;
}
__device__ __forceinline__ void ldsm_x4(uint32_t& r0, uint32_t& r1, uint32_t& r2,
                                        uint32_t& r3, uint32_t addr) {
    asm volatile("ldmatrix.sync.aligned.m8n8.x4.shared.b16 {%0,%1,%2,%3}, [%4];"
                 : "=r"(r0), "=r"(r1), "=r"(r2), "=r"(r3) : "r"(addr));
}
__device__ __forceinline__ void mma_bf16(float* c, const uint32_t* a, const uint32_t* b) {
    asm volatile("mma.sync.aligned.m16n8k16.row.col.f32.bf16.bf16.f32 "
                 "{%0,%1,%2,%3}, {%4,%5,%6,%7}, {%8,%9}, {%0,%1,%2,%3};"
                 : "+f"(c[0]), "+f"(c[1]), "+f"(c[2]), "+f"(c[3])
                 : "r"(a[0]), "r"(a[1]), "r"(a[2]), "r"(a[3]), "r"(b[0]), "r"(b[1]));
}
__device__ __forceinline__ void red_add_v2(float* p, float x, float y) {
    asm volatile("red.global.add.v2.f32 [%0], {%1, %2};"
                 :: "l"(p), "f"(x), "f"(y) : "memory");
}
__device__ __forceinline__ void cp_async16(uint32_t saddr, const void* gptr) {
    asm volatile("cp.async.cg.shared.global [%0], [%1], 16;"
                 :: "r"(saddr), "l"(gptr) : "memory");
}
#define CP_COMMIT() asm volatile("cp.async.commit_group;" ::: "memory")
#define CP_WAIT(n)  asm volatile("cp.async.wait_group %0;" :: "n"(n) : "memory")

// ---------------------------------------------------------------------------
// K0: zero output accumulator + histograms
// ---------------------------------------------------------------------------
__global__ void zero_kernel(float4* __restrict__ out) {
    size_t i = (size_t)blockIdx.x * blockDim.x + threadIdx.x;
    const size_t tot4 = (size_t)NNODES * DIM / 4;
    if (i < tot4) out[i] = make_float4(0.f, 0.f, 0.f, 0.f);
    if (i < NNODES) g_dcnt[i] = 0;
    if (i < NRELS) g_cnt16[i] = 0;
}

// ---------------------------------------------------------------------------
// K1: split A = emb[node_ids] into hi/lo bf16
// ---------------------------------------------------------------------------
__global__ __launch_bounds__(256)
void split_a_kernel(const float* __restrict__ emb, const int* __restrict__ node_ids) {
    size_t t = (size_t)blockIdx.x * blockDim.x + threadIdx.x;  // over N*D/4
    const size_t tot = (size_t)NNODES * (DIM / 4);
    if (t >= tot) return;
    int row = (int)(t >> 6);
    int c4  = (int)(t & 63);
    int nid = node_ids[row];
    float4 v = ((const float4*)(emb + (size_t)nid * DIM))[c4];
    __nv_bfloat16 hx = __float2bfloat16(v.x), hy = __float2bfloat16(v.y);
    __nv_bfloat16 hz = __float2bfloat16(v.z), hw = __float2bfloat16(v.w);
    __nv_bfloat16 lx = __float2bfloat16(v.x - __bfloat162float(hx));
    __nv_bfloat16 ly = __float2bfloat16(v.y - __bfloat162float(hy));
    __nv_bfloat16 lz = __float2bfloat16(v.z - __bfloat162float(hz));
    __nv_bfloat16 lw = __float2bfloat16(v.w - __bfloat162float(hw));
    __nv_bfloat162* ph = (__nv_bfloat162*)g_Ah;
    __nv_bfloat162* pl = (__nv_bfloat162*)g_Al;
    ph[t * 2]     = __nv_bfloat162{hx, hy};
    ph[t * 2 + 1] = __nv_bfloat162{hz, hw};
    pl[t * 2]     = __nv_bfloat162{lx, ly};
    pl[t * 2 + 1] = __nv_bfloat162{lz, lw};
}

// ---------------------------------------------------------------------------
// K2: build W^T[r][n][k] = sum_b w_comp[r,b] * basis[b][k][n], split hi/lo
// ---------------------------------------------------------------------------
__global__ __launch_bounds__(256)
void build_w_kernel(const float* __restrict__ basis, const float* __restrict__ w_comp) {
    __shared__ float wc[NRELS * NBASES];
    if (threadIdx.x < NRELS * NBASES) wc[threadIdx.x] = w_comp[threadIdx.x];
    __syncthreads();
    int idx = blockIdx.x * blockDim.x + threadIdx.x;   // 65536 = (n,k)
    if (idx >= DIM * DIM) return;
    int n = idx >> 8;
    int k = idx & 255;
    float bv[NBASES];
    #pragma unroll
    for (int b = 0; b < NBASES; b++)
        bv[b] = __ldg(basis + (size_t)b * DIM * DIM + (size_t)k * DIM + n);
    #pragma unroll
    for (int r = 0; r < NRELS; r++) {
        float x = 0.f;
        #pragma unroll
        for (int b = 0; b < NBASES; b++) x = fmaf(wc[r * NBASES + b], bv[b], x);
        __nv_bfloat16 h = __float2bfloat16(x);
        __nv_bfloat16 l = __float2bfloat16(x - __bfloat162float(h));
        g_Wth[(size_t)r * DIM * DIM + idx] = h;
        g_Wtl[(size_t)r * DIM * DIM + idx] = l;
    }
}

// ---------------------------------------------------------------------------
// K3: histograms (etype bucket counts smem-aggregated; dst in-degree direct)
// ---------------------------------------------------------------------------
__global__ __launch_bounds__(256)
void ehist_kernel(const int* __restrict__ et, const int* __restrict__ dst) {
    __shared__ int h[NRELS];
    if (threadIdx.x < NRELS) h[threadIdx.x] = 0;
    __syncthreads();
    int e = blockIdx.x * blockDim.x + threadIdx.x;
    if (e < NEDGES) {
        atomicAdd(&h[et[e]], 1);
        atomicAdd(&g_dcnt[dst[e]], 1);
    }
    __syncthreads();
    if (threadIdx.x < NRELS) atomicAdd(&g_cnt16[threadIdx.x], h[threadIdx.x]);
}

// ---------------------------------------------------------------------------
// K4: tiny scan over 16 buckets (1 warp)
// ---------------------------------------------------------------------------
__global__ void scan16_kernel() {
    int lane = threadIdx.x;
    int c = (lane < NRELS) ? g_cnt16[lane] : 0;
    int p = (lane < NRELS) ? ((c + 127) & ~127) : 0;
    int xc = c, xp = p;
    #pragma unroll
    for (int d = 1; d < 32; d <<= 1) {
        int yc = __shfl_up_sync(0xffffffffu, xc, d);
        int yp = __shfl_up_sync(0xffffffffu, xp, d);
        if (lane >= d) { xc += yc; xp += yp; }
    }
    if (lane < NRELS) {
        g_start16[lane] = xc - c;
        g_cur16[lane]   = xc - c;
        g_pstart[lane]  = xp - p;
    }
    if (lane == NRELS) g_pstart[NRELS] = xp;   // inclusive total of padded counts
}

// ---------------------------------------------------------------------------
// K5: fill relation permutation (block-ranked counting sort)
// ---------------------------------------------------------------------------
__global__ __launch_bounds__(256)
void fill_kernel(const int* __restrict__ et) {
    __shared__ int h[NRELS], base[NRELS];
    if (threadIdx.x < NRELS) h[threadIdx.x] = 0;
    __syncthreads();
    int e = blockIdx.x * blockDim.x + threadIdx.x;
    int r = 0, rank = 0;
    if (e < NEDGES) {
        r = et[e];
        rank = atomicAdd(&h[r], 1);
    }
    __syncthreads();
    if (threadIdx.x < NRELS)
        base[threadIdx.x] = atomicAdd(&g_cur16[threadIdx.x], h[threadIdx.x]);
    __syncthreads();
    if (e < NEDGES) g_perm[base[r] + rank] = e;
}

// ---------------------------------------------------------------------------
// K6: PERSISTENT fused GEMM+scatter, 512 threads (16 warps = 4/SMSP).
//  Warp grid 4m x 4n, warp tile 32x32.  B operand (W^T half, 132 KB)
//  resident across tiles sharing (r, n0h); A streams cp.async
//  double-buffered; epilogue = norm-scaled red.add.v2 into out[dst].
// ---------------------------------------------------------------------------
#define A_PAD      72
#define A_SPLIT_B  (128 * A_PAD * 2)        // 18432 B per split
#define A_STAGE_B  (2 * A_SPLIT_B)          // 36864 B per stage
#define B_PAD      264
#define B_SPLIT_B  (128 * B_PAD * 2)        // 67584 B per split
#define SM_B_OFF   (2 * A_STAGE_B)          // 73728
#define SM_META_OFF (SM_B_OFF + 2 * B_SPLIT_B)   // 208896
#define SM_TOTAL   (SM_META_OFF + 1536)     // 210432 bytes
#define NCTA_PERSIST 148
#define NTHREADS   512

__global__ __launch_bounds__(NTHREADS, 1)
void gemm_persist_kernel(const int* __restrict__ src,
                         const int* __restrict__ dst,
                         const float* __restrict__ norm,
                         float* __restrict__ out) {
    extern __shared__ char smem[];
    int*   s_src  = (int*)(smem + SM_META_OFF);
    int*   s_dst  = (int*)(smem + SM_META_OFF + 512);
    float* s_norm = (float*)(smem + SM_META_OFF + 1024);
    const uint32_t smAu = smem_to_u32(smem);
    const uint32_t smBu = smAu + SM_B_OFF;

    const int tid  = threadIdx.x;
    const int lane = tid & 31;
    const int w    = tid >> 5;
    const int mw   = w >> 2;        // 0..3  (32-row band)
    const int nw   = w & 3;         // 0..3  (32-col band)

    const int Ptot = g_pstart[NRELS] >> 7;       // total 128-row blocks
    const int T = 2 * Ptot;                       // x2 n-halves
    const int t_begin = (int)((long long)T * blockIdx.x / gridDim.x);
    const int t_end   = (int)((long long)T * (blockIdx.x + 1) / gridDim.x);

    int cur_key = -1;

    for (int t = t_begin; t < t_end; t++) {
        // ---- decode tile -> (r, n0h, blk) from g_pstart ----
        int r = 0;
        #pragma unroll
        for (int i = 1; i < NRELS; i++)
            if (t >= 2 * (g_pstart[i] >> 7)) r = i;
        const int Pr = g_pstart[r] >> 7;
        const int Tr = (g_pstart[r + 1] >> 7) - Pr;
        const int local = t - 2 * Pr;
        const int n0h = (local >= Tr) ? 1 : 0;
        const int blk = local - n0h * Tr;

        __syncthreads();   // all warps past previous tile's epilogue/smem reads

        // ---- B residency: reload only when (r, n0h) changes ----
        const int key = r * 2 + n0h;
        if (key != cur_key) {
            cur_key = key;
            const __nv_bfloat16* Wh = g_Wth + (size_t)r * DIM * DIM + (size_t)n0h * 128 * DIM;
            const __nv_bfloat16* Wl = g_Wtl + (size_t)r * DIM * DIM + (size_t)n0h * 128 * DIM;
            #pragma unroll
            for (int it = 0; it < 16; it++) {
                int i = it * NTHREADS + tid;      // 0..8191
                int split = i >> 12;
                int rem = i & 4095;
                int nrow = rem >> 5;
                int kg = (rem & 31) * 8;          // element offset
                const __nv_bfloat16* gp = (split ? Wl : Wh) + (size_t)nrow * DIM + kg;
                cp_async16(smBu + split * B_SPLIT_B + nrow * (B_PAD * 2) + kg * 2, gp);
            }
            CP_COMMIT();
            CP_WAIT(0);
        }

        // ---- edge metadata ----
        if (tid < 128) {
            int local_e = blk * 128 + tid;
            int e = (local_e < g_cnt16[r]) ? g_perm[g_start16[r] + local_e] : -1;
            s_src[tid]  = (e >= 0) ? __ldg(src + e) : 0;
            s_dst[tid]  = (e >= 0) ? __ldg(dst + e) : -1;
            s_norm[tid] = (e >= 0) ? __ldg(norm + e) : 0.f;
        }
        __syncthreads();

        // ---- A chunk issue (2048 16B ops, 4 per thread) ----
        #define A_ISSUE(KC, ST) do {                                              \
            int kbase_ = (KC) * 64;                                                \
            _Pragma("unroll")                                                      \
            for (int it_ = 0; it_ < 4; it_++) {                                    \
                int i_ = it_ * NTHREADS + tid;                                     \
                int split_ = i_ >> 10;                                             \
                int rem_ = i_ & 1023;                                              \
                int row_ = rem_ >> 3;                                              \
                int kg_ = (rem_ & 7) * 8;                                          \
                const __nv_bfloat16* ga_ = split_ ? g_Al : g_Ah;                   \
                const __nv_bfloat16* gp_ = ga_ + (size_t)s_src[row_] * DIM + kbase_ + kg_; \
                cp_async16(smAu + (ST) * A_STAGE_B + split_ * A_SPLIT_B +          \
                           (row_ * A_PAD + kg_) * 2, gp_);                         \
            }                                                                      \
            CP_COMMIT();                                                           \
        } while (0)

        A_ISSUE(0, 0);

        float acc[2][4][4];
        #pragma unroll
        for (int i = 0; i < 2; i++)
            #pragma unroll
            for (int j = 0; j < 4; j++)
                #pragma unroll
                for (int k = 0; k < 4; k++) acc[i][j][k] = 0.f;

        for (int kc = 0; kc < 4; kc++) {
            if (kc < 3) {
                if (kc == 0)      A_ISSUE(1, 1);
                else if (kc == 1) A_ISSUE(2, 0);
                else              A_ISSUE(3, 1);
                CP_WAIT(1);
            } else {
                CP_WAIT(0);
            }
            __syncthreads();

            const uint32_t sA = smAu + (kc & 1) * A_STAGE_B;
            #pragma unroll
            for (int kk = 0; kk < 4; kk++) {
                const int kof = kk * 16 + ((lane >> 4) << 3);
                uint32_t ah[2][4], al[2][4];
                #pragma unroll
                for (int mi = 0; mi < 2; mi++) {
                    int row = mw * 32 + mi * 16 + (lane & 15);
                    uint32_t adr = sA + (uint32_t)(row * A_PAD + kof) * 2;
                    ldsm_x4(ah[mi][0], ah[mi][1], ah[mi][2], ah[mi][3], adr);
                    ldsm_x4(al[mi][0], al[mi][1], al[mi][2], al[mi][3],
                            adr + A_SPLIT_B);
                }
                const int kof_b = kc * 64 + kk * 16 + (((lane >> 3) & 1) << 3);
                #pragma unroll
                for (int nt2 = 0; nt2 < 2; nt2++) {
                    int nrow = nw * 32 + (nt2 * 2 + ((lane >> 4) & 1)) * 8 + (lane & 7);
                    uint32_t adr = smBu + (uint32_t)(nrow * B_PAD + kof_b) * 2;
                    uint32_t bh[4], bl[4];
                    ldsm_x4(bh[0], bh[1], bh[2], bh[3], adr);
                    ldsm_x4(bl[0], bl[1], bl[2], bl[3], adr + B_SPLIT_B);
                    #pragma unroll
                    for (int p = 0; p < 2; p++) {
                        int nt = nt2 * 2 + p;
                        #pragma unroll
                        for (int mi = 0; mi < 2; mi++) {
                            mma_bf16(acc[mi][nt], ah[mi], &bh[2 * p]);
                            mma_bf16(acc[mi][nt], al[mi], &bh[2 * p]);
                            mma_bf16(acc[mi][nt], ah[mi], &bl[2 * p]);
                        }
                    }
                }
            }
            __syncthreads();   // stage consumed before it is refilled
        }
        #undef A_ISSUE

        // ---- epilogue: direct red.add.v2, scaled by norm ----
        const int qrow = lane >> 2;
        const int qcol = (lane & 3) * 2;
        const int colbase = n0h * 128 + nw * 32;
        #pragma unroll
        for (int mi = 0; mi < 2; mi++) {
            int lr0 = mw * 32 + mi * 16 + qrow;
            int lr1 = lr0 + 8;
            int d0 = s_dst[lr0], d1 = s_dst[lr1];
            float nm0 = s_norm[lr0], nm1 = s_norm[lr1];
            float* o0 = out + (size_t)d0 * DIM + colbase;
            float* o1 = out + (size_t)d1 * DIM + colbase;
            #pragma unroll
            for (int nt = 0; nt < 4; nt++) {
                float* c = acc[mi][nt];
                int col = nt * 8 + qcol;
                if (d0 >= 0) red_add_v2(o0 + col, c[0] * nm0, c[1] * nm0);
                if (d1 >= 0) red_add_v2(o1 + col, c[2] * nm1, c[3] * nm1);
            }
        }
    }
}

// ---------------------------------------------------------------------------
// K7: finalize  out = (deg>0 ? out/deg : 0) + bias
// ---------------------------------------------------------------------------
__global__ __launch_bounds__(256)
void finalize_kernel(const float* __restrict__ bias, float4* __restrict__ out) {
    size_t idx = (size_t)blockIdx.x * blockDim.x + threadIdx.x;
    const size_t tot4 = (size_t)NNODES * DIM / 4;
    if (idx >= tot4) return;
    int n  = (int)(idx >> 6);
    int d4 = (int)(idx & 63);
    int cnt = g_dcnt[n];
    float inv = (cnt > 0) ? (1.0f / (float)cnt) : 0.0f;
    float4 v = out[idx];
    float4 bb = ((const float4*)bias)[d4];
    v.x = fmaf(v.x, inv, bb.x);
    v.y = fmaf(v.y, inv, bb.y);
    v.z = fmaf(v.z, inv, bb.z);
    v.w = fmaf(v.w, inv, bb.w);
    out[idx] = v;
}

// ---------------------------------------------------------------------------
// kernel_launch
// Inputs (metadata order): node_ids[i32,N], src[i32,E], dst[i32,E],
//   etypes[i32,E], norm[f32,E], emb[f32,N*D], basis[f32,B*D*D],
//   w_comp[f32,R*B], h_bias[f32,D].  Output: f32 [N, D].
// ---------------------------------------------------------------------------
extern "C" void kernel_launch(void* const* d_in, const int* in_sizes, int n_in,
                              void* d_out, int out_size) {
    const int*   node_ids = (const int*)  d_in[0];
    const int*   src      = (const int*)  d_in[1];
    const int*   dst      = (const int*)  d_in[2];
    const int*   etypes   = (const int*)  d_in[3];
    const float* norm     = (const float*)d_in[4];
    const float* emb      = (const float*)d_in[5];
    const float* basis    = (const float*)d_in[6];
    const float* w_comp   = (const float*)d_in[7];
    const float* h_bias   = (const float*)d_in[8];
    float* out = (float*)d_out;

    const int tot4 = NNODES * DIM / 4;
    const int blk4 = (tot4 + 255) / 256;

    cudaFuncSetAttribute(gemm_persist_kernel,
                         cudaFuncAttributeMaxDynamicSharedMemorySize, SM_TOTAL);

    zero_kernel<<<blk4, 256>>>((float4*)out);
    split_a_kernel<<<blk4, 256>>>(emb, node_ids);
    build_w_kernel<<<(DIM * DIM + 255) / 256, 256>>>(basis, w_comp);

    ehist_kernel<<<(NEDGES + 255) / 256, 256>>>(etypes, dst);
    scan16_kernel<<<1, 32>>>();
    fill_kernel<<<(NEDGES + 255) / 256, 256>>>(etypes);

    gemm_persist_kernel<<<NCTA_PERSIST, NTHREADS, SM_TOTAL>>>(src, dst, norm, out);

    finalize_kernel<<<blk4, 256>>>(h_bias, (float4*)out);
}

// round 14
// speedup vs baseline: 1.1410x; 1.0688x over previous
#include <cuda_runtime.h>
#include <cuda_bf16.h>
#include <cstdint>

// Problem constants
#define NNODES 100000
#define DIM    256
#define NBASES 8
#define NRELS  16
#define NEDGES 800000

// ---------------------------------------------------------------------------
// Static device scratch (~105 MB)
// ---------------------------------------------------------------------------
__device__ __nv_bfloat16 g_Ah[(size_t)NNODES * DIM];         // 51.2 MB hi(emb[node_ids])
__device__ __nv_bfloat16 g_Al[(size_t)NNODES * DIM];         // 51.2 MB lo residual
__device__ __nv_bfloat16 g_Wth[(size_t)NRELS * DIM * DIM];   // 2 MB hi(W[r]^T) [r][n][k]
__device__ __nv_bfloat16 g_Wtl[(size_t)NRELS * DIM * DIM];   // 2 MB lo residual
__device__ int g_dcnt[NNODES];        // in-degree (dst histogram)
__device__ int g_cnt16[NRELS];        // relation histogram
__device__ int g_start16[NRELS];      // bucket starts (exclusive scan)
__device__ int g_cur16[NRELS];        // fill cursors
__device__ int g_pstart[NRELS + 1];   // padded bucket starts (multiples of 128)
__device__ int g_perm[NEDGES];        // edge ids sorted by relation

// ---------------------------------------------------------------------------
// PTX helpers (compute_100-safe: ldmatrix + mma.sync + cp.async, NO tcgen05)
// ---------------------------------------------------------------------------
__device__ __forceinline__ uint32_t smem_to_u32(const void* p) {
    uint32_t a;
    asm("{ .reg .u64 t; cvta.to.shared.u64 t, %1; cvt.u32.u64 %0, t; }" : "=r"(a) : "l"(p));
    return a;
}
__device__ __forceinline__ void ldsm_x4(uint32_t& r0, uint32_t& r1, uint32_t& r2,
                                        uint32_t& r3, uint32_t addr) {
    asm volatile("ldmatrix.sync.aligned.m8n8.x4.shared.b16 {%0,%1,%2,%3}, [%4];"
                 : "=r"(r0), "=r"(r1), "=r"(r2), "=r"(r3) : "r"(addr));
}
__device__ __forceinline__ void ldsm_x2(uint32_t& r0, uint32_t& r1, uint32_t addr) {
    asm volatile("ldmatrix.sync.aligned.m8n8.x2.shared.b16 {%0,%1}, [%2];"
                 : "=r"(r0), "=r"(r1) : "r"(addr));
}
__device__ __forceinline__ void mma_bf16(float* c, const uint32_t* a, const uint32_t* b) {
    asm volatile("mma.sync.aligned.m16n8k16.row.col.f32.bf16.bf16.f32 "
                 "{%0,%1,%2,%3}, {%4,%5,%6,%7}, {%8,%9}, {%0,%1,%2,%3};"
                 : "+f"(c[0]), "+f"(c[1]), "+f"(c[2]), "+f"(c[3])
                 : "r"(a[0]), "r"(a[1]), "r"(a[2]), "r"(a[3]), "r"(b[0]), "r"(b[1]));
}
__device__ __forceinline__ void red_add_v4(float4* p, float4 v) {
    asm volatile("red.global.add.v4.f32 [%0], {%1, %2, %3, %4};"
                 :: "l"(p), "f"(v.x), "f"(v.y), "f"(v.z), "f"(v.w) : "memory");
}
__device__ __forceinline__ void cp_async16(uint32_t saddr, const void* gptr) {
    asm volatile("cp.async.cg.shared.global [%0], [%1], 16;"
                 :: "r"(saddr), "l"(gptr) : "memory");
}
#define CP_COMMIT() asm volatile("cp.async.commit_group;" ::: "memory")
#define CP_WAIT(n)  asm volatile("cp.async.wait_group %0;" :: "n"(n) : "memory")

// ---------------------------------------------------------------------------
// K0: zero output accumulator + histograms
// ---------------------------------------------------------------------------
__global__ void zero_kernel(float4* __restrict__ out) {
    size_t i = (size_t)blockIdx.x * blockDim.x + threadIdx.x;
    const size_t tot4 = (size_t)NNODES * DIM / 4;
    if (i < tot4) out[i] = make_float4(0.f, 0.f, 0.f, 0.f);
    if (i < NNODES) g_dcnt[i] = 0;
    if (i < NRELS) g_cnt16[i] = 0;
}

// ---------------------------------------------------------------------------
// K1: split A = emb[node_ids] into hi/lo bf16
// ---------------------------------------------------------------------------
__global__ __launch_bounds__(256)
void split_a_kernel(const float* __restrict__ emb, const int* __restrict__ node_ids) {
    size_t t = (size_t)blockIdx.x * blockDim.x + threadIdx.x;  // over N*D/4
    const size_t tot = (size_t)NNODES * (DIM / 4);
    if (t >= tot) return;
    int row = (int)(t >> 6);
    int c4  = (int)(t & 63);
    int nid = node_ids[row];
    float4 v = ((const float4*)(emb + (size_t)nid * DIM))[c4];
    __nv_bfloat16 hx = __float2bfloat16(v.x), hy = __float2bfloat16(v.y);
    __nv_bfloat16 hz = __float2bfloat16(v.z), hw = __float2bfloat16(v.w);
    __nv_bfloat16 lx = __float2bfloat16(v.x - __bfloat162float(hx));
    __nv_bfloat16 ly = __float2bfloat16(v.y - __bfloat162float(hy));
    __nv_bfloat16 lz = __float2bfloat16(v.z - __bfloat162float(hz));
    __nv_bfloat16 lw = __float2bfloat16(v.w - __bfloat162float(hw));
    __nv_bfloat162* ph = (__nv_bfloat162*)g_Ah;
    __nv_bfloat162* pl = (__nv_bfloat162*)g_Al;
    ph[t * 2]     = __nv_bfloat162{hx, hy};
    ph[t * 2 + 1] = __nv_bfloat162{hz, hw};
    pl[t * 2]     = __nv_bfloat162{lx, ly};
    pl[t * 2 + 1] = __nv_bfloat162{lz, lw};
}

// ---------------------------------------------------------------------------
// K2: build W^T[r][n][k] = sum_b w_comp[r,b] * basis[b][k][n], split hi/lo
// ---------------------------------------------------------------------------
__global__ __launch_bounds__(256)
void build_w_kernel(const float* __restrict__ basis, const float* __restrict__ w_comp) {
    __shared__ float wc[NRELS * NBASES];
    if (threadIdx.x < NRELS * NBASES) wc[threadIdx.x] = w_comp[threadIdx.x];
    __syncthreads();
    int idx = blockIdx.x * blockDim.x + threadIdx.x;   // 65536 = (n,k)
    if (idx >= DIM * DIM) return;
    int n = idx >> 8;
    int k = idx & 255;
    float bv[NBASES];
    #pragma unroll
    for (int b = 0; b < NBASES; b++)
        bv[b] = __ldg(basis + (size_t)b * DIM * DIM + (size_t)k * DIM + n);
    #pragma unroll
    for (int r = 0; r < NRELS; r++) {
        float x = 0.f;
        #pragma unroll
        for (int b = 0; b < NBASES; b++) x = fmaf(wc[r * NBASES + b], bv[b], x);
        __nv_bfloat16 h = __float2bfloat16(x);
        __nv_bfloat16 l = __float2bfloat16(x - __bfloat162float(h));
        g_Wth[(size_t)r * DIM * DIM + idx] = h;
        g_Wtl[(size_t)r * DIM * DIM + idx] = l;
    }
}

// ---------------------------------------------------------------------------
// K3: histograms (etype bucket counts smem-aggregated; dst in-degree direct)
// ---------------------------------------------------------------------------
__global__ __launch_bounds__(256)
void ehist_kernel(const int* __restrict__ et, const int* __restrict__ dst) {
    __shared__ int h[NRELS];
    if (threadIdx.x < NRELS) h[threadIdx.x] = 0;
    __syncthreads();
    int e = blockIdx.x * blockDim.x + threadIdx.x;
    if (e < NEDGES) {
        atomicAdd(&h[et[e]], 1);
        atomicAdd(&g_dcnt[dst[e]], 1);
    }
    __syncthreads();
    if (threadIdx.x < NRELS) atomicAdd(&g_cnt16[threadIdx.x], h[threadIdx.x]);
}

// ---------------------------------------------------------------------------
// K4: tiny scan over 16 buckets (1 warp)
// ---------------------------------------------------------------------------
__global__ void scan16_kernel() {
    int lane = threadIdx.x;
    int c = (lane < NRELS) ? g_cnt16[lane] : 0;
    int p = (lane < NRELS) ? ((c + 127) & ~127) : 0;
    int xc = c, xp = p;
    #pragma unroll
    for (int d = 1; d < 32; d <<= 1) {
        int yc = __shfl_up_sync(0xffffffffu, xc, d);
        int yp = __shfl_up_sync(0xffffffffu, xp, d);
        if (lane >= d) { xc += yc; xp += yp; }
    }
    if (lane < NRELS) {
        g_start16[lane] = xc - c;
        g_cur16[lane]   = xc - c;
        g_pstart[lane]  = xp - p;
    }
    if (lane == NRELS) g_pstart[NRELS] = xp;   // inclusive total of padded counts
}

// ---------------------------------------------------------------------------
// K5: fill relation permutation (block-ranked counting sort)
// ---------------------------------------------------------------------------
__global__ __launch_bounds__(256)
void fill_kernel(const int* __restrict__ et) {
    __shared__ int h[NRELS], base[NRELS];
    if (threadIdx.x < NRELS) h[threadIdx.x] = 0;
    __syncthreads();
    int e = blockIdx.x * blockDim.x + threadIdx.x;
    int r = 0, rank = 0;
    if (e < NEDGES) {
        r = et[e];
        rank = atomicAdd(&h[r], 1);
    }
    __syncthreads();
    if (threadIdx.x < NRELS)
        base[threadIdx.x] = atomicAdd(&g_cur16[threadIdx.x], h[threadIdx.x]);
    __syncthreads();
    if (e < NEDGES) g_perm[base[r] + rank] = e;
}

// ---------------------------------------------------------------------------
// K6: PERSISTENT fused GEMM+scatter (R10 config: 256 threads, 8 warps 4m x 2n).
//  B operand (W^T half, 132 KB) resident across tiles sharing (r, n0h);
//  A streams cp.async double-buffered.
//  NEW (R14): epilogue stages norm-scaled tile into SMEM (A region, free after
//  last kc) and drains with row-coalesced red.add.v4 — halves REDG lane-ops.
// ---------------------------------------------------------------------------
#define A_PAD      72
#define A_SPLIT_B  (128 * A_PAD * 2)        // 18432 B per split
#define A_STAGE_B  (2 * A_SPLIT_B)          // 36864 B per stage
#define B_PAD      264
#define B_SPLIT_B  (128 * B_PAD * 2)        // 67584 B per split
#define SM_B_OFF   (2 * A_STAGE_B)          // 73728
#define SM_META_OFF (SM_B_OFF + 2 * B_SPLIT_B)   // 208896
#define SM_TOTAL   (SM_META_OFF + 1536)     // 210432 bytes
#define NCTA_PERSIST 148

__global__ __launch_bounds__(256)
void gemm_persist_kernel(const int* __restrict__ src,
                         const int* __restrict__ dst,
                         const float* __restrict__ norm,
                         float* __restrict__ out) {
    extern __shared__ char smem[];
    int*   s_src  = (int*)(smem + SM_META_OFF);
    int*   s_dst  = (int*)(smem + SM_META_OFF + 512);
    float* s_norm = (float*)(smem + SM_META_OFF + 1024);
    float* stg    = (float*)smem;             // overlays A stages post-compute
    const uint32_t smAu = smem_to_u32(smem);
    const uint32_t smBu = smAu + SM_B_OFF;

    const int tid  = threadIdx.x;
    const int lane = tid & 31;
    const int w    = tid >> 5;
    const int mw   = w >> 1;        // 0..3
    const int nw   = w & 1;         // 0..1

    const int Ptot = g_pstart[NRELS] >> 7;       // total 128-row blocks
    const int T = 2 * Ptot;                       // x2 n-halves
    const int t_begin = (int)((long long)T * blockIdx.x / gridDim.x);
    const int t_end   = (int)((long long)T * (blockIdx.x + 1) / gridDim.x);

    int cur_key = -1;

    for (int t = t_begin; t < t_end; t++) {
        // ---- decode tile -> (r, n0h, blk) from g_pstart ----
        int r = 0;
        #pragma unroll
        for (int i = 1; i < NRELS; i++)
            if (t >= 2 * (g_pstart[i] >> 7)) r = i;
        const int Pr = g_pstart[r] >> 7;
        const int Tr = (g_pstart[r + 1] >> 7) - Pr;
        const int local = t - 2 * Pr;
        const int n0h = (local >= Tr) ? 1 : 0;
        const int blk = local - n0h * Tr;

        __syncthreads();   // all warps past previous tile's epilogue/smem reads

        // ---- B residency: reload only when (r, n0h) changes ----
        const int key = r * 2 + n0h;
        if (key != cur_key) {
            cur_key = key;
            const __nv_bfloat16* Wh = g_Wth + (size_t)r * DIM * DIM + (size_t)n0h * 128 * DIM;
            const __nv_bfloat16* Wl = g_Wtl + (size_t)r * DIM * DIM + (size_t)n0h * 128 * DIM;
            #pragma unroll
            for (int it = 0; it < 32; it++) {
                int i = it * 256 + tid;           // 0..8191
                int split = i >> 12;
                int rem = i & 4095;
                int nrow = rem >> 5;
                int kg = (rem & 31) * 8;          // element offset
                const __nv_bfloat16* gp = (split ? Wl : Wh) + (size_t)nrow * DIM + kg;
                cp_async16(smBu + split * B_SPLIT_B + nrow * (B_PAD * 2) + kg * 2, gp);
            }
            CP_COMMIT();
            CP_WAIT(0);
        }

        // ---- edge metadata ----
        if (tid < 128) {
            int local_e = blk * 128 + tid;
            int e = (local_e < g_cnt16[r]) ? g_perm[g_start16[r] + local_e] : -1;
            s_src[tid]  = (e >= 0) ? __ldg(src + e) : 0;
            s_dst[tid]  = (e >= 0) ? __ldg(dst + e) : -1;
            s_norm[tid] = (e >= 0) ? __ldg(norm + e) : 0.f;
        }
        __syncthreads();

        // ---- A chunk issue helper (kc chunk into stage st) ----
        #define A_ISSUE(KC, ST) do {                                              \
            int kbase_ = (KC) * 64;                                                \
            _Pragma("unroll")                                                      \
            for (int it_ = 0; it_ < 8; it_++) {                                    \
                int i_ = it_ * 256 + tid;                                          \
                int split_ = i_ >> 10;                                             \
                int rem_ = i_ & 1023;                                              \
                int row_ = rem_ >> 3;                                              \
                int kg_ = (rem_ & 7) * 8;                                          \
                const __nv_bfloat16* ga_ = split_ ? g_Al : g_Ah;                   \
                const __nv_bfloat16* gp_ = ga_ + (size_t)s_src[row_] * DIM + kbase_ + kg_; \
                cp_async16(smAu + (ST) * A_STAGE_B + split_ * A_SPLIT_B +          \
                           (row_ * A_PAD + kg_) * 2, gp_);                         \
            }                                                                      \
            CP_COMMIT();                                                           \
        } while (0)

        A_ISSUE(0, 0);

        float acc[2][8][4];
        #pragma unroll
        for (int i = 0; i < 2; i++)
            #pragma unroll
            for (int j = 0; j < 8; j++)
                #pragma unroll
                for (int k = 0; k < 4; k++) acc[i][j][k] = 0.f;

        for (int kc = 0; kc < 4; kc++) {
            if (kc < 3) {
                if (kc == 0)      A_ISSUE(1, 1);
                else if (kc == 1) A_ISSUE(2, 0);
                else              A_ISSUE(3, 1);
                CP_WAIT(1);
            } else {
                CP_WAIT(0);
            }
            __syncthreads();

            const uint32_t sA = smAu + (kc & 1) * A_STAGE_B;
            #pragma unroll
            for (int kk = 0; kk < 4; kk++) {
                const int kof = kk * 16 + ((lane >> 4) << 3);
                uint32_t ah[2][4], al[2][4];
                #pragma unroll
                for (int mi = 0; mi < 2; mi++) {
                    int row = mw * 32 + mi * 16 + (lane & 15);
                    uint32_t adr = sA + (uint32_t)(row * A_PAD + kof) * 2;
                    ldsm_x4(ah[mi][0], ah[mi][1], ah[mi][2], ah[mi][3], adr);
                    ldsm_x4(al[mi][0], al[mi][1], al[mi][2], al[mi][3],
                            adr + A_SPLIT_B);
                }
                const int kof_b = kc * 64 + kk * 16 + (((lane >> 3) & 1) << 3);
                #pragma unroll
                for (int nt2 = 0; nt2 < 4; nt2++) {
                    int nrow = nw * 64 + (nt2 * 2 + ((lane >> 4) & 1)) * 8 + (lane & 7);
                    uint32_t adr = smBu + (uint32_t)(nrow * B_PAD + kof_b) * 2;
                    uint32_t bh[4], bl[4];
                    ldsm_x4(bh[0], bh[1], bh[2], bh[3], adr);
                    ldsm_x4(bl[0], bl[1], bl[2], bl[3], adr + B_SPLIT_B);
                    #pragma unroll
                    for (int p = 0; p < 2; p++) {
                        int nt = nt2 * 2 + p;
                        #pragma unroll
                        for (int mi = 0; mi < 2; mi++) {
                            mma_bf16(acc[mi][nt], ah[mi], &bh[2 * p]);
                            mma_bf16(acc[mi][nt], al[mi], &bh[2 * p]);
                            mma_bf16(acc[mi][nt], ah[mi], &bl[2 * p]);
                        }
                    }
                }
            }
            __syncthreads();   // stage consumed before refill; also frees A for stg
        }
        #undef A_ISSUE

        // ---- epilogue: scale by norm, stage to SMEM (A region), drain with
        //      row-coalesced red.add.v4 (half the REDG lane-ops of v2) ----
        const int qrow = lane >> 2;
        const int qcol = (lane & 3) * 2;
        #pragma unroll
        for (int mi = 0; mi < 2; mi++) {
            int lr0 = mw * 32 + mi * 16 + qrow;
            int lr1 = lr0 + 8;
            float nm0 = s_norm[lr0];
            float nm1 = s_norm[lr1];
            #pragma unroll
            for (int nt = 0; nt < 8; nt++) {
                float* c = acc[mi][nt];
                int colL = nw * 64 + nt * 8 + qcol;
                *(float2*)&stg[lr0 * 132 + colL] = make_float2(c[0] * nm0, c[1] * nm0);
                *(float2*)&stg[lr1 * 132 + colL] = make_float2(c[2] * nm1, c[3] * nm1);
            }
        }
        __syncthreads();

        const int colbase = n0h * 128;
        #pragma unroll
        for (int rr = 0; rr < 16; rr++) {
            int row = w * 16 + rr;
            int d = s_dst[row];
            if (d < 0) continue;
            float4 v = *(float4*)&stg[row * 132 + lane * 4];
            red_add_v4((float4*)(out + (size_t)d * DIM + colbase + lane * 4), v);
        }
    }
}

// ---------------------------------------------------------------------------
// K7: finalize  out = (deg>0 ? out/deg : 0) + bias
// ---------------------------------------------------------------------------
__global__ __launch_bounds__(256)
void finalize_kernel(const float* __restrict__ bias, float4* __restrict__ out) {
    size_t idx = (size_t)blockIdx.x * blockDim.x + threadIdx.x;
    const size_t tot4 = (size_t)NNODES * DIM / 4;
    if (idx >= tot4) return;
    int n  = (int)(idx >> 6);
    int d4 = (int)(idx & 63);
    int cnt = g_dcnt[n];
    float inv = (cnt > 0) ? (1.0f / (float)cnt) : 0.0f;
    float4 v = out[idx];
    float4 bb = ((const float4*)bias)[d4];
    v.x = fmaf(v.x, inv, bb.x);
    v.y = fmaf(v.y, inv, bb.y);
    v.z = fmaf(v.z, inv, bb.z);
    v.w = fmaf(v.w, inv, bb.w);
    out[idx] = v;
}

// ---------------------------------------------------------------------------
// kernel_launch
// Inputs (metadata order): node_ids[i32,N], src[i32,E], dst[i32,E],
//   etypes[i32,E], norm[f32,E], emb[f32,N*D], basis[f32,B*D*D],
//   w_comp[f32,R*B], h_bias[f32,D].  Output: f32 [N, D].
// ---------------------------------------------------------------------------
extern "C" void kernel_launch(void* const* d_in, const int* in_sizes, int n_in,
                              void* d_out, int out_size) {
    const int*   node_ids = (const int*)  d_in[0];
    const int*   src      = (const int*)  d_in[1];
    const int*   dst      = (const int*)  d_in[2];
    const int*   etypes   = (const int*)  d_in[3];
    const float* norm     = (const float*)d_in[4];
    const float* emb      = (const float*)d_in[5];
    const float* basis    = (const float*)d_in[6];
    const float* w_comp   = (const float*)d_in[7];
    const float* h_bias   = (const float*)d_in[8];
    float* out = (float*)d_out;

    const int tot4 = NNODES * DIM / 4;
    const int blk4 = (tot4 + 255) / 256;

    cudaFuncSetAttribute(gemm_persist_kernel,
                         cudaFuncAttributeMaxDynamicSharedMemorySize, SM_TOTAL);

    zero_kernel<<<blk4, 256>>>((float4*)out);
    split_a_kernel<<<blk4, 256>>>(emb, node_ids);
    build_w_kernel<<<(DIM * DIM + 255) / 256, 256>>>(basis, w_comp);

    ehist_kernel<<<(NEDGES + 255) / 256, 256>>>(etypes, dst);
    scan16_kernel<<<1, 32>>>();
    fill_kernel<<<(NEDGES + 255) / 256, 256>>>(etypes);

    gemm_persist_kernel<<<NCTA_PERSIST, 256, SM_TOTAL>>>(src, dst, norm, out);

    finalize_kernel<<<blk4, 256>>>(h_bias, (float4*)out);
}

// round 15
// speedup vs baseline: 2.1219x; 1.8597x over previous
#include <cuda_runtime.h>
#include <cuda_fp16.h>
#include <cstdint>

// Problem constants
#define NNODES 100000
#define DIM    256
#define NBASES 8
#define NRELS  16
#define NEDGES 800000

// ---------------------------------------------------------------------------
// Static device scratch (~55 MB)
// ---------------------------------------------------------------------------
__device__ __half g_A[(size_t)NNODES * DIM];          // 51.2 MB fp16(emb[node_ids])
__device__ __half g_W[(size_t)NRELS * DIM * DIM];     // 2 MB fp16(W[r]^T) [r][n][k]
__device__ int g_dcnt[NNODES];        // in-degree (dst histogram)
__device__ int g_cnt16[NRELS];        // relation histogram
__device__ int g_start16[NRELS];      // bucket starts (exclusive scan)
__device__ int g_cur16[NRELS];        // fill cursors
__device__ int g_pstart[NRELS + 1];   // padded bucket starts (multiples of 128)
__device__ int g_perm[NEDGES];        // edge ids sorted by relation

// ---------------------------------------------------------------------------
// PTX helpers (compute_100-safe: ldmatrix + mma.sync + cp.async, NO tcgen05)
// ---------------------------------------------------------------------------
__device__ __forceinline__ uint32_t smem_to_u32(const void* p) {
    uint32_t a;
    asm("{ .reg .u64 t; cvta.to.shared.u64 t, %1; cvt.u32.u64 %0, t; }" : "=r"(a) : "l"(p));
    return a;
}
__device__ __forceinline__ void ldsm_x4(uint32_t& r0, uint32_t& r1, uint32_t& r2,
                                        uint32_t& r3, uint32_t addr) {
    asm volatile("ldmatrix.sync.aligned.m8n8.x4.shared.b16 {%0,%1,%2,%3}, [%4];"
                 : "=r"(r0), "=r"(r1), "=r"(r2), "=r"(r3) : "r"(addr));
}
__device__ __forceinline__ void mma_fp16(float* c, const uint32_t* a, const uint32_t* b) {
    asm volatile("mma.sync.aligned.m16n8k16.row.col.f32.f16.f16.f32 "
                 "{%0,%1,%2,%3}, {%4,%5,%6,%7}, {%8,%9}, {%0,%1,%2,%3};"
                 : "+f"(c[0]), "+f"(c[1]), "+f"(c[2]), "+f"(c[3])
                 : "r"(a[0]), "r"(a[1]), "r"(a[2]), "r"(a[3]), "r"(b[0]), "r"(b[1]));
}
__device__ __forceinline__ void red_add_v2(float* p, float x, float y) {
    asm volatile("red.global.add.v2.f32 [%0], {%1, %2};"
                 :: "l"(p), "f"(x), "f"(y) : "memory");
}
__device__ __forceinline__ void cp_async16(uint32_t saddr, const void* gptr) {
    asm volatile("cp.async.cg.shared.global [%0], [%1], 16;"
                 :: "r"(saddr), "l"(gptr) : "memory");
}
#define CP_COMMIT() asm volatile("cp.async.commit_group;" ::: "memory")
#define CP_WAIT(n)  asm volatile("cp.async.wait_group %0;" :: "n"(n) : "memory")

// ---------------------------------------------------------------------------
// K0: zero output accumulator + histograms
// ---------------------------------------------------------------------------
__global__ void zero_kernel(float4* __restrict__ out) {
    size_t i = (size_t)blockIdx.x * blockDim.x + threadIdx.x;
    const size_t tot4 = (size_t)NNODES * DIM / 4;
    if (i < tot4) out[i] = make_float4(0.f, 0.f, 0.f, 0.f);
    if (i < NNODES) g_dcnt[i] = 0;
    if (i < NRELS) g_cnt16[i] = 0;
}

// ---------------------------------------------------------------------------
// K1: convert A = emb[node_ids] to fp16
// ---------------------------------------------------------------------------
__global__ __launch_bounds__(256)
void conv_a_kernel(const float* __restrict__ emb, const int* __restrict__ node_ids) {
    size_t t = (size_t)blockIdx.x * blockDim.x + threadIdx.x;  // over N*D/4
    const size_t tot = (size_t)NNODES * (DIM / 4);
    if (t >= tot) return;
    int row = (int)(t >> 6);
    int c4  = (int)(t & 63);
    int nid = node_ids[row];
    float4 v = ((const float4*)(emb + (size_t)nid * DIM))[c4];
    __half2* ph = (__half2*)g_A;
    ph[t * 2]     = __floats2half2_rn(v.x, v.y);
    ph[t * 2 + 1] = __floats2half2_rn(v.z, v.w);
}

// ---------------------------------------------------------------------------
// K2: build W^T[r][n][k] = sum_b w_comp[r,b] * basis[b][k][n], fp16
//     idx = (n<<8)|k so writes are k-contiguous (coalesced).
// ---------------------------------------------------------------------------
__global__ __launch_bounds__(256)
void build_w_kernel(const float* __restrict__ basis, const float* __restrict__ w_comp) {
    __shared__ float wc[NRELS * NBASES];
    if (threadIdx.x < NRELS * NBASES) wc[threadIdx.x] = w_comp[threadIdx.x];
    __syncthreads();
    int idx = blockIdx.x * blockDim.x + threadIdx.x;   // 65536 = (n,k)
    if (idx >= DIM * DIM) return;
    int n = idx >> 8;
    int k = idx & 255;
    float bv[NBASES];
    #pragma unroll
    for (int b = 0; b < NBASES; b++)
        bv[b] = __ldg(basis + (size_t)b * DIM * DIM + (size_t)k * DIM + n);
    #pragma unroll
    for (int r = 0; r < NRELS; r++) {
        float x = 0.f;
        #pragma unroll
        for (int b = 0; b < NBASES; b++) x = fmaf(wc[r * NBASES + b], bv[b], x);
        g_W[(size_t)r * DIM * DIM + idx] = __float2half_rn(x);
    }
}

// ---------------------------------------------------------------------------
// K3: histograms (etype bucket counts smem-aggregated; dst in-degree direct)
// ---------------------------------------------------------------------------
__global__ __launch_bounds__(256)
void ehist_kernel(const int* __restrict__ et, const int* __restrict__ dst) {
    __shared__ int h[NRELS];
    if (threadIdx.x < NRELS) h[threadIdx.x] = 0;
    __syncthreads();
    int e = blockIdx.x * blockDim.x + threadIdx.x;
    if (e < NEDGES) {
        atomicAdd(&h[et[e]], 1);
        atomicAdd(&g_dcnt[dst[e]], 1);
    }
    __syncthreads();
    if (threadIdx.x < NRELS) atomicAdd(&g_cnt16[threadIdx.x], h[threadIdx.x]);
}

// ---------------------------------------------------------------------------
// K4: tiny scan over 16 buckets (1 warp)
// ---------------------------------------------------------------------------
__global__ void scan16_kernel() {
    int lane = threadIdx.x;
    int c = (lane < NRELS) ? g_cnt16[lane] : 0;
    int p = (lane < NRELS) ? ((c + 127) & ~127) : 0;
    int xc = c, xp = p;
    #pragma unroll
    for (int d = 1; d < 32; d <<= 1) {
        int yc = __shfl_up_sync(0xffffffffu, xc, d);
        int yp = __shfl_up_sync(0xffffffffu, xp, d);
        if (lane >= d) { xc += yc; xp += yp; }
    }
    if (lane < NRELS) {
        g_start16[lane] = xc - c;
        g_cur16[lane]   = xc - c;
        g_pstart[lane]  = xp - p;
    }
    if (lane == NRELS) g_pstart[NRELS] = xp;   // inclusive total of padded counts
}

// ---------------------------------------------------------------------------
// K5: fill relation permutation (block-ranked counting sort)
// ---------------------------------------------------------------------------
__global__ __launch_bounds__(256)
void fill_kernel(const int* __restrict__ et) {
    __shared__ int h[NRELS], base[NRELS];
    if (threadIdx.x < NRELS) h[threadIdx.x] = 0;
    __syncthreads();
    int e = blockIdx.x * blockDim.x + threadIdx.x;
    int r = 0, rank = 0;
    if (e < NEDGES) {
        r = et[e];
        rank = atomicAdd(&h[r], 1);
    }
    __syncthreads();
    if (threadIdx.x < NRELS)
        base[threadIdx.x] = atomicAdd(&g_cur16[threadIdx.x], h[threadIdx.x]);
    __syncthreads();
    if (e < NEDGES) g_perm[base[r] + rank] = e;
}

// ---------------------------------------------------------------------------
// K6: PERSISTENT fused GEMM+scatter, single-term fp16.
//  Tile = 128 edges x FULL N=256 cols, K=256.  W[r] (256n x 256k fp16,
//  135 KB) resident in SMEM across all tiles of relation r -> A gathered
//  exactly once per edge, cp.async double-buffered in 64-k chunks.
//  8 warps (4m x 2n), warp tile 32x128.  Epilogue: norm-scaled red.add.v2.
// ---------------------------------------------------------------------------
#define A_PAD      72
#define A_STAGE_B  (128 * A_PAD * 2)        // 18432 B per stage
#define B_PAD      264
#define SM_B_OFF   (2 * A_STAGE_B)          // 36864
#define B_BYTES    (256 * B_PAD * 2)        // 135168
#define SM_META_OFF (SM_B_OFF + B_BYTES)    // 172032
#define SM_TOTAL   (SM_META_OFF + 1536)     // 173568 bytes
#define NCTA_PERSIST 148

__global__ __launch_bounds__(256)
void gemm_persist_kernel(const int* __restrict__ src,
                         const int* __restrict__ dst,
                         const float* __restrict__ norm,
                         float* __restrict__ out) {
    extern __shared__ char smem[];
    int*   s_src  = (int*)(smem + SM_META_OFF);
    int*   s_dst  = (int*)(smem + SM_META_OFF + 512);
    float* s_norm = (float*)(smem + SM_META_OFF + 1024);
    const uint32_t smAu = smem_to_u32(smem);
    const uint32_t smBu = smAu + SM_B_OFF;

    const int tid  = threadIdx.x;
    const int lane = tid & 31;
    const int w    = tid >> 5;
    const int mw   = w >> 1;        // 0..3  (32-row band)
    const int nw   = w & 1;         // 0..1  (128-col band)

    const int T = g_pstart[NRELS] >> 7;          // total 128-edge tiles
    const int t_begin = (int)((long long)T * blockIdx.x / gridDim.x);
    const int t_end   = (int)((long long)T * (blockIdx.x + 1) / gridDim.x);

    int cur_r = -1;

    for (int t = t_begin; t < t_end; t++) {
        // ---- decode tile -> (r, blk) from g_pstart ----
        int r = 0;
        #pragma unroll
        for (int i = 1; i < NRELS; i++)
            if (t >= (g_pstart[i] >> 7)) r = i;
        const int blk = t - (g_pstart[r] >> 7);

        __syncthreads();   // all warps past previous tile's epilogue/smem reads

        // ---- B residency: reload only when relation changes ----
        if (r != cur_r) {
            cur_r = r;
            const __half* Wp = g_W + (size_t)r * DIM * DIM;
            #pragma unroll
            for (int it = 0; it < 33; it++) {
                int i = it * 256 + tid;           // 0..8447
                if (i < 256 * 32) {
                    int nrow = i >> 5;
                    int kg = (i & 31) * 8;        // element offset
                    cp_async16(smBu + nrow * (B_PAD * 2) + kg * 2,
                               Wp + (size_t)nrow * DIM + kg);
                }
            }
            CP_COMMIT();
            CP_WAIT(0);
        }

        // ---- edge metadata ----
        if (tid < 128) {
            int local_e = blk * 128 + tid;
            int e = (local_e < g_cnt16[r]) ? g_perm[g_start16[r] + local_e] : -1;
            s_src[tid]  = (e >= 0) ? __ldg(src + e) : 0;
            s_dst[tid]  = (e >= 0) ? __ldg(dst + e) : -1;
            s_norm[tid] = (e >= 0) ? __ldg(norm + e) : 0.f;
        }
        __syncthreads();

        // ---- A chunk issue (1024 16B ops, 4 per thread) ----
        #define A_ISSUE(KC, ST) do {                                              \
            int kbase_ = (KC) * 64;                                                \
            _Pragma("unroll")                                                      \
            for (int it_ = 0; it_ < 4; it_++) {                                    \
                int i_ = it_ * 256 + tid;                                          \
                int row_ = i_ >> 3;                                                \
                int kg_ = (i_ & 7) * 8;                                            \
                const __half* gp_ = g_A + (size_t)s_src[row_] * DIM + kbase_ + kg_;\
                cp_async16(smAu + (ST) * A_STAGE_B + (row_ * A_PAD + kg_) * 2, gp_);\
            }                                                                      \
            CP_COMMIT();                                                           \
        } while (0)

        A_ISSUE(0, 0);

        float acc[2][16][4];
        #pragma unroll
        for (int i = 0; i < 2; i++)
            #pragma unroll
            for (int j = 0; j < 16; j++)
                #pragma unroll
                for (int k = 0; k < 4; k++) acc[i][j][k] = 0.f;

        for (int kc = 0; kc < 4; kc++) {
            if (kc < 3) {
                if (kc == 0)      A_ISSUE(1, 1);
                else if (kc == 1) A_ISSUE(2, 0);
                else              A_ISSUE(3, 1);
                CP_WAIT(1);
            } else {
                CP_WAIT(0);
            }
            __syncthreads();

            const uint32_t sA = smAu + (kc & 1) * A_STAGE_B;
            #pragma unroll
            for (int kk = 0; kk < 4; kk++) {
                const int kof = kk * 16 + ((lane >> 4) << 3);
                uint32_t a[2][4];
                #pragma unroll
                for (int mi = 0; mi < 2; mi++) {
                    int row = mw * 32 + mi * 16 + (lane & 15);
                    uint32_t adr = sA + (uint32_t)(row * A_PAD + kof) * 2;
                    ldsm_x4(a[mi][0], a[mi][1], a[mi][2], a[mi][3], adr);
                }
                const int kof_b = kc * 64 + kk * 16 + (((lane >> 3) & 1) << 3);
                #pragma unroll
                for (int nt2 = 0; nt2 < 8; nt2++) {
                    int nrow = nw * 128 + (nt2 * 2 + ((lane >> 4) & 1)) * 8 + (lane & 7);
                    uint32_t adr = smBu + (uint32_t)(nrow * B_PAD + kof_b) * 2;
                    uint32_t b[4];
                    ldsm_x4(b[0], b[1], b[2], b[3], adr);
                    #pragma unroll
                    for (int p = 0; p < 2; p++) {
                        int nt = nt2 * 2 + p;
                        #pragma unroll
                        for (int mi = 0; mi < 2; mi++)
                            mma_fp16(acc[mi][nt], a[mi], &b[2 * p]);
                    }
                }
            }
            __syncthreads();   // stage consumed before it is refilled
        }
        #undef A_ISSUE

        // ---- epilogue: direct red.add.v2, scaled by norm ----
        const int qrow = lane >> 2;
        const int qcol = (lane & 3) * 2;
        const int colbase = nw * 128;
        #pragma unroll
        for (int mi = 0; mi < 2; mi++) {
            int lr0 = mw * 32 + mi * 16 + qrow;
            int lr1 = lr0 + 8;
            int d0 = s_dst[lr0], d1 = s_dst[lr1];
            float nm0 = s_norm[lr0], nm1 = s_norm[lr1];
            float* o0 = out + (size_t)d0 * DIM + colbase;
            float* o1 = out + (size_t)d1 * DIM + colbase;
            #pragma unroll
            for (int nt = 0; nt < 16; nt++) {
                float* c = acc[mi][nt];
                int col = nt * 8 + qcol;
                if (d0 >= 0) red_add_v2(o0 + col, c[0] * nm0, c[1] * nm0);
                if (d1 >= 0) red_add_v2(o1 + col, c[2] * nm1, c[3] * nm1);
            }
        }
    }
}

// ---------------------------------------------------------------------------
// K7: finalize  out = (deg>0 ? out/deg : 0) + bias
// ---------------------------------------------------------------------------
__global__ __launch_bounds__(256)
void finalize_kernel(const float* __restrict__ bias, float4* __restrict__ out) {
    size_t idx = (size_t)blockIdx.x * blockDim.x + threadIdx.x;
    const size_t tot4 = (size_t)NNODES * DIM / 4;
    if (idx >= tot4) return;
    int n  = (int)(idx >> 6);
    int d4 = (int)(idx & 63);
    int cnt = g_dcnt[n];
    float inv = (cnt > 0) ? (1.0f / (float)cnt) : 0.0f;
    float4 v = out[idx];
    float4 bb = ((const float4*)bias)[d4];
    v.x = fmaf(v.x, inv, bb.x);
    v.y = fmaf(v.y, inv, bb.y);
    v.z = fmaf(v.z, inv, bb.z);
    v.w = fmaf(v.w, inv, bb.w);
    out[idx] = v;
}

// ---------------------------------------------------------------------------
// kernel_launch
// Inputs (metadata order): node_ids[i32,N], src[i32,E], dst[i32,E],
//   etypes[i32,E], norm[f32,E], emb[f32,N*D], basis[f32,B*D*D],
//   w_comp[f32,R*B], h_bias[f32,D].  Output: f32 [N, D].
// ---------------------------------------------------------------------------
extern "C" void kernel_launch(void* const* d_in, const int* in_sizes, int n_in,
                              void* d_out, int out_size) {
    const int*   node_ids = (const int*)  d_in[0];
    const int*   src      = (const int*)  d_in[1];
    const int*   dst      = (const int*)  d_in[2];
    const int*   etypes   = (const int*)  d_in[3];
    const float* norm     = (const float*)d_in[4];
    const float* emb      = (const float*)d_in[5];
    const float* basis    = (const float*)d_in[6];
    const float* w_comp   = (const float*)d_in[7];
    const float* h_bias   = (const float*)d_in[8];
    float* out = (float*)d_out;

    const int tot4 = NNODES * DIM / 4;
    const int blk4 = (tot4 + 255) / 256;

    cudaFuncSetAttribute(gemm_persist_kernel,
                         cudaFuncAttributeMaxDynamicSharedMemorySize, SM_TOTAL);

    zero_kernel<<<blk4, 256>>>((float4*)out);
    conv_a_kernel<<<blk4, 256>>>(emb, node_ids);
    build_w_kernel<<<(DIM * DIM + 255) / 256, 256>>>(basis, w_comp);

    ehist_kernel<<<(NEDGES + 255) / 256, 256>>>(etypes, dst);
    scan16_kernel<<<1, 32>>>();
    fill_kernel<<<(NEDGES + 255) / 256, 256>>>(etypes);

    gemm_persist_kernel<<<NCTA_PERSIST, 256, SM_TOTAL>>>(src, dst, norm, out);

    finalize_kernel<<<blk4, 256>>>(h_bias, (float4*)out);
}

// round 17
// speedup vs baseline: 2.4426x; 1.1511x over previous
#include <cuda_runtime.h>
#include <cuda_fp16.h>
#include <cstdint>

// Problem constants
#define NNODES 100000
#define DIM    256
#define NBASES 8
#define NRELS  16
#define NEDGES 800000

// ---------------------------------------------------------------------------
// Static device scratch (~55 MB)
// ---------------------------------------------------------------------------
__device__ __half g_A[(size_t)NNODES * DIM];          // 51.2 MB fp16(emb[node_ids])
__device__ __half g_W[(size_t)NRELS * DIM * DIM];     // 2 MB fp16(W[r]^T) [r][n][k]
__device__ int g_dcnt[NNODES];        // in-degree (dst histogram)
__device__ int g_cnt16[NRELS];        // relation histogram
__device__ int g_start16[NRELS];      // bucket starts (exclusive scan)
__device__ int g_cur16[NRELS];        // fill cursors
__device__ int g_pstart[NRELS + 1];   // padded bucket starts (multiples of 128)
__device__ int g_perm[NEDGES];        // edge ids sorted by relation

// ---------------------------------------------------------------------------
// PTX helpers (compute_100-safe: ldmatrix + mma.sync + cp.async, NO tcgen05)
// ---------------------------------------------------------------------------
__device__ __forceinline__ uint32_t smem_to_u32(const void* p) {
    uint32_t a;
    asm("{ .reg .u64 t; cvta.to.shared.u64 t, %1; cvt.u32.u64 %0, t; }" : "=r"(a) : "l"(p));
    return a;
}
__device__ __forceinline__ void ldsm_x4(uint32_t& r0, uint32_t& r1, uint32_t& r2,
                                        uint32_t& r3, uint32_t addr) {
    asm volatile("ldmatrix.sync.aligned.m8n8.x4.shared.b16 {%0,%1,%2,%3}, [%4];"
                 : "=r"(r0), "=r"(r1), "=r"(r2), "=r"(r3) : "r"(addr));
}
__device__ __forceinline__ void mma_fp16(float* c, const uint32_t* a, const uint32_t* b) {
    asm volatile("mma.sync.aligned.m16n8k16.row.col.f32.f16.f16.f32 "
                 "{%0,%1,%2,%3}, {%4,%5,%6,%7}, {%8,%9}, {%0,%1,%2,%3};"
                 : "+f"(c[0]), "+f"(c[1]), "+f"(c[2]), "+f"(c[3])
                 : "r"(a[0]), "r"(a[1]), "r"(a[2]), "r"(a[3]), "r"(b[0]), "r"(b[1]));
}
__device__ __forceinline__ void red_add_v2(float* p, float x, float y) {
    asm volatile("red.global.add.v2.f32 [%0], {%1, %2};"
                 :: "l"(p), "f"(x), "f"(y) : "memory");
}
__device__ __forceinline__ void cp_async16(uint32_t saddr, const void* gptr) {
    asm volatile("cp.async.cg.shared.global [%0], [%1], 16;"
                 :: "r"(saddr), "l"(gptr) : "memory");
}
#define CP_COMMIT() asm volatile("cp.async.commit_group;" ::: "memory")
#define CP_WAIT(n)  asm volatile("cp.async.wait_group %0;" :: "n"(n) : "memory")

// ---------------------------------------------------------------------------
// K1: zero out/histograms + convert A = emb[node_ids] to fp16 (fused)
// ---------------------------------------------------------------------------
__global__ __launch_bounds__(256)
void prep_kernel(const float* __restrict__ emb, const int* __restrict__ node_ids,
                 float4* __restrict__ out) {
    size_t t = (size_t)blockIdx.x * blockDim.x + threadIdx.x;  // over N*D/4
    const size_t tot = (size_t)NNODES * (DIM / 4);
    if (t < NNODES) g_dcnt[t] = 0;
    if (t < NRELS) g_cnt16[t] = 0;
    if (t >= tot) return;
    out[t] = make_float4(0.f, 0.f, 0.f, 0.f);
    int row = (int)(t >> 6);
    int c4  = (int)(t & 63);
    int nid = node_ids[row];
    float4 v = ((const float4*)(emb + (size_t)nid * DIM))[c4];
    __half2* ph = (__half2*)g_A;
    ph[t * 2]     = __floats2half2_rn(v.x, v.y);
    ph[t * 2 + 1] = __floats2half2_rn(v.z, v.w);
}

// ---------------------------------------------------------------------------
// K2: build W^T[r][n][k] = sum_b w_comp[r,b] * basis[b][k][n], fp16
// ---------------------------------------------------------------------------
__global__ __launch_bounds__(256)
void build_w_kernel(const float* __restrict__ basis, const float* __restrict__ w_comp) {
    __shared__ float wc[NRELS * NBASES];
    if (threadIdx.x < NRELS * NBASES) wc[threadIdx.x] = w_comp[threadIdx.x];
    __syncthreads();
    int idx = blockIdx.x * blockDim.x + threadIdx.x;   // 65536 = (n,k)
    if (idx >= DIM * DIM) return;
    int n = idx >> 8;
    int k = idx & 255;
    float bv[NBASES];
    #pragma unroll
    for (int b = 0; b < NBASES; b++)
        bv[b] = __ldg(basis + (size_t)b * DIM * DIM + (size_t)k * DIM + n);
    #pragma unroll
    for (int r = 0; r < NRELS; r++) {
        float x = 0.f;
        #pragma unroll
        for (int b = 0; b < NBASES; b++) x = fmaf(wc[r * NBASES + b], bv[b], x);
        g_W[(size_t)r * DIM * DIM + idx] = __float2half_rn(x);
    }
}

// ---------------------------------------------------------------------------
// K3: histograms (etype bucket counts smem-aggregated; dst in-degree direct)
// ---------------------------------------------------------------------------
__global__ __launch_bounds__(256)
void ehist_kernel(const int* __restrict__ et, const int* __restrict__ dst) {
    __shared__ int h[NRELS];
    if (threadIdx.x < NRELS) h[threadIdx.x] = 0;
    __syncthreads();
    int e = blockIdx.x * blockDim.x + threadIdx.x;
    if (e < NEDGES) {
        atomicAdd(&h[et[e]], 1);
        atomicAdd(&g_dcnt[dst[e]], 1);
    }
    __syncthreads();
    if (threadIdx.x < NRELS) atomicAdd(&g_cnt16[threadIdx.x], h[threadIdx.x]);
}

// ---------------------------------------------------------------------------
// K4: tiny scan over 16 buckets (1 warp)
// ---------------------------------------------------------------------------
__global__ void scan16_kernel() {
    int lane = threadIdx.x;
    int c = (lane < NRELS) ? g_cnt16[lane] : 0;
    int p = (lane < NRELS) ? ((c + 127) & ~127) : 0;
    int xc = c, xp = p;
    #pragma unroll
    for (int d = 1; d < 32; d <<= 1) {
        int yc = __shfl_up_sync(0xffffffffu, xc, d);
        int yp = __shfl_up_sync(0xffffffffu, xp, d);
        if (lane >= d) { xc += yc; xp += yp; }
    }
    if (lane < NRELS) {
        g_start16[lane] = xc - c;
        g_cur16[lane]   = xc - c;
        g_pstart[lane]  = xp - p;
    }
    if (lane == NRELS) g_pstart[NRELS] = xp;   // inclusive total of padded counts
}

// ---------------------------------------------------------------------------
// K5: fill relation permutation (block-ranked counting sort)
// ---------------------------------------------------------------------------
__global__ __launch_bounds__(256)
void fill_kernel(const int* __restrict__ et) {
    __shared__ int h[NRELS], base[NRELS];
    if (threadIdx.x < NRELS) h[threadIdx.x] = 0;
    __syncthreads();
    int e = blockIdx.x * blockDim.x + threadIdx.x;
    int r = 0, rank = 0;
    if (e < NEDGES) {
        r = et[e];
        rank = atomicAdd(&h[r], 1);
    }
    __syncthreads();
    if (threadIdx.x < NRELS)
        base[threadIdx.x] = atomicAdd(&g_cur16[threadIdx.x], h[threadIdx.x]);
    __syncthreads();
    if (e < NEDGES) g_perm[base[r] + rank] = e;
}

// ---------------------------------------------------------------------------
// K6: PERSISTENT fused GEMM+scatter, fp16, CROSS-TILE SOFTWARE PIPELINE.
//  Tile = 128 edges x N=256, K=256.  W[r] (135 KB) resident per relation.
//  A cp.async double-buffered in 64-k chunks.
//   - next tile's edge metadata prefetched into regs during kc0, staged to a
//     double-buffered SMEM slot during kc2,
//   - next tile's A chunk0 issued right after kc2 (flies behind kc3+epilogue),
//  so tile boundaries expose no LDG/cp.async latency.
// ---------------------------------------------------------------------------
#define A_PAD      72
#define A_STAGE_B  (128 * A_PAD * 2)        // 18432 B per stage
#define B_PAD      264
#define SM_B_OFF   (2 * A_STAGE_B)          // 36864
#define B_BYTES    (256 * B_PAD * 2)        // 135168
#define SM_META_OFF (SM_B_OFF + B_BYTES)    // 172032
// meta: 2 x (src,dst int[128], norm float[128]) = 3072, tables 256
#define SM_TOTAL   (SM_META_OFF + 3072 + 256)
#define NCTA_PERSIST 148

__global__ __launch_bounds__(256)
void gemm_persist_kernel(const int* __restrict__ src,
                         const int* __restrict__ dst,
                         const float* __restrict__ norm,
                         float* __restrict__ out) {
    extern __shared__ char smem[];
    int*   s_src  = (int*)(smem + SM_META_OFF);            // [2][128]
    int*   s_dst  = (int*)(smem + SM_META_OFF + 1024);     // [2][128]
    float* s_norm = (float*)(smem + SM_META_OFF + 2048);   // [2][128]
    int*   s_ps   = (int*)(smem + SM_META_OFF + 3072);     // [17]
    int*   s_cnt  = s_ps + 17;                             // [16]
    int*   s_st   = s_ps + 33;                             // [16]
    const uint32_t smAu = smem_to_u32(smem);
    const uint32_t smBu = smAu + SM_B_OFF;

    const int tid  = threadIdx.x;
    const int lane = tid & 31;
    const int w    = tid >> 5;
    const int mw   = w >> 1;        // 0..3  (32-row band)
    const int nw   = w & 1;         // 0..1  (128-col band)

    // cache bucket tables
    if (tid < 17) s_ps[tid] = g_pstart[tid];
    if (tid < 16) { s_cnt[tid] = g_cnt16[tid]; s_st[tid] = g_start16[tid]; }
    __syncthreads();

    const int T = s_ps[NRELS] >> 7;              // total 128-edge tiles
    const int t_begin = (int)((long long)T * blockIdx.x / gridDim.x);
    const int t_end   = (int)((long long)T * (blockIdx.x + 1) / gridDim.x);
    if (t_begin >= t_end) return;

    // ---- prologue: meta for t_begin + A chunk0 in flight ----
    {
        int mb = t_begin & 1;
        int r0 = 0;
        #pragma unroll
        for (int i = 1; i < NRELS; i++) if (t_begin >= (s_ps[i] >> 7)) r0 = i;
        int blk0 = t_begin - (s_ps[r0] >> 7);
        if (tid < 128) {
            int le = blk0 * 128 + tid;
            int e = (le < s_cnt[r0]) ? __ldg(g_perm + s_st[r0] + le) : -1;
            s_src[mb * 128 + tid]  = (e >= 0) ? __ldg(src + e) : 0;
            s_dst[mb * 128 + tid]  = (e >= 0) ? __ldg(dst + e) : -1;
            s_norm[mb * 128 + tid] = (e >= 0) ? __ldg(norm + e) : 0.f;
        }
        __syncthreads();
        // A chunk0 -> stage0
        #pragma unroll
        for (int it_ = 0; it_ < 4; it_++) {
            int i_ = it_ * 256 + tid;
            int row_ = i_ >> 3;
            int kg_ = (i_ & 7) * 8;
            const __half* gp_ = g_A + (size_t)s_src[mb * 128 + row_] * DIM + kg_;
            cp_async16(smAu + (row_ * A_PAD + kg_) * 2, gp_);
        }
        CP_COMMIT();
    }

    int cur_r = -1;

    #define A_ISSUE(KC, ST, MB) do {                                              \
        int kbase_ = (KC) * 64;                                                    \
        _Pragma("unroll")                                                          \
        for (int it_ = 0; it_ < 4; it_++) {                                        \
            int i_ = it_ * 256 + tid;                                              \
            int row_ = i_ >> 3;                                                    \
            int kg_ = (i_ & 7) * 8;                                                \
            const __half* gp_ = g_A + (size_t)s_src[(MB) * 128 + row_] * DIM + kbase_ + kg_; \
            cp_async16(smAu + (ST) * A_STAGE_B + (row_ * A_PAD + kg_) * 2, gp_);   \
        }                                                                          \
        CP_COMMIT();                                                               \
    } while (0)

    #define COMPUTE(KC) do {                                                       \
        const uint32_t sA = smAu + ((KC) & 1) * A_STAGE_B;                         \
        _Pragma("unroll")                                                          \
        for (int kk = 0; kk < 4; kk++) {                                           \
            const int kof = kk * 16 + ((lane >> 4) << 3);                          \
            uint32_t a[2][4];                                                      \
            _Pragma("unroll")                                                      \
            for (int mi = 0; mi < 2; mi++) {                                       \
                int row = mw * 32 + mi * 16 + (lane & 15);                         \
                uint32_t adr = sA + (uint32_t)(row * A_PAD + kof) * 2;             \
                ldsm_x4(a[mi][0], a[mi][1], a[mi][2], a[mi][3], adr);              \
            }                                                                      \
            const int kof_b = (KC) * 64 + kk * 16 + (((lane >> 3) & 1) << 3);      \
            _Pragma("unroll")                                                      \
            for (int nt2 = 0; nt2 < 8; nt2++) {                                    \
                int nrow = nw * 128 + (nt2 * 2 + ((lane >> 4) & 1)) * 8 + (lane & 7); \
                uint32_t adr = smBu + (uint32_t)(nrow * B_PAD + kof_b) * 2;        \
                uint32_t b[4];                                                     \
                ldsm_x4(b[0], b[1], b[2], b[3], adr);                              \
                _Pragma("unroll")                                                  \
                for (int p = 0; p < 2; p++) {                                      \
                    int nt = nt2 * 2 + p;                                          \
                    _Pragma("unroll")                                              \
                    for (int mi = 0; mi < 2; mi++)                                 \
                        mma_fp16(acc[mi][nt], a[mi], &b[2 * p]);                   \
                }                                                                  \
            }                                                                      \
        }                                                                          \
    } while (0)

    for (int t = t_begin; t < t_end; t++) {
        const int mb = t & 1;
        int r = 0;
        #pragma unroll
        for (int i = 1; i < NRELS; i++) if (t >= (s_ps[i] >> 7)) r = i;

        // ---- B residency: reload only when relation changes ----
        if (r != cur_r) {
            cur_r = r;
            const __half* Wp = g_W + (size_t)r * DIM * DIM;
            #pragma unroll
            for (int it = 0; it < 33; it++) {
                int i = it * 256 + tid;
                if (i < 256 * 32) {
                    int nrow = i >> 5;
                    int kg = (i & 31) * 8;
                    cp_async16(smBu + nrow * (B_PAD * 2) + kg * 2,
                               Wp + (size_t)nrow * DIM + kg);
                }
            }
            CP_COMMIT();
            CP_WAIT(0);
        }

        const bool has_next = (t + 1 < t_end);

        float acc[2][16][4];
        #pragma unroll
        for (int i = 0; i < 2; i++)
            #pragma unroll
            for (int j = 0; j < 16; j++)
                #pragma unroll
                for (int k = 0; k < 4; k++) acc[i][j][k] = 0.f;

        // ---- kc0 ----
        A_ISSUE(1, 1, mb);
        CP_WAIT(1);
        __syncthreads();
        // next tile meta -> registers (latency hidden by kc0+kc1 compute)
        int s2v = 0, d2v = -1; float n2v = 0.f;
        if (has_next && tid < 128) {
            int tn = t + 1;
            int r2 = 0;
            #pragma unroll
            for (int i = 1; i < NRELS; i++) if (tn >= (s_ps[i] >> 7)) r2 = i;
            int le2 = (tn - (s_ps[r2] >> 7)) * 128 + tid;
            int e2 = (le2 < s_cnt[r2]) ? __ldg(g_perm + s_st[r2] + le2) : -1;
            if (e2 >= 0) {
                s2v = __ldg(src + e2);
                d2v = __ldg(dst + e2);
                n2v = __ldg(norm + e2);
            }
        }
        COMPUTE(0);
        __syncthreads();

        // ---- kc1 ----
        A_ISSUE(2, 0, mb);
        CP_WAIT(1);
        __syncthreads();
        COMPUTE(1);
        __syncthreads();

        // ---- kc2 ----
        A_ISSUE(3, 1, mb);
        CP_WAIT(1);
        __syncthreads();
        if (has_next && tid < 128) {        // stage next meta (published by kc2-end sync)
            int nb = mb ^ 1;
            s_src[nb * 128 + tid]  = s2v;
            s_dst[nb * 128 + tid]  = d2v;
            s_norm[nb * 128 + tid] = n2v;
        }
        COMPUTE(2);
        __syncthreads();

        // ---- kc3: next tile's A chunk0 flies behind compute + epilogue ----
        if (has_next) {
            A_ISSUE(0, 0, mb ^ 1);
            CP_WAIT(1);
        } else {
            CP_WAIT(0);
        }
        __syncthreads();
        COMPUTE(3);
        __syncthreads();

        // ---- epilogue: direct red.add.v2, scaled by norm ----
        const int qrow = lane >> 2;
        const int qcol = (lane & 3) * 2;
        const int colbase = nw * 128;
        #pragma unroll
        for (int mi = 0; mi < 2; mi++) {
            int lr0 = mw * 32 + mi * 16 + qrow;
            int lr1 = lr0 + 8;
            int d0 = s_dst[mb * 128 + lr0], d1 = s_dst[mb * 128 + lr1];
            float nm0 = s_norm[mb * 128 + lr0], nm1 = s_norm[mb * 128 + lr1];
            float* o0 = out + (size_t)d0 * DIM + colbase;
            float* o1 = out + (size_t)d1 * DIM + colbase;
            #pragma unroll
            for (int nt = 0; nt < 16; nt++) {
                float* c = acc[mi][nt];
                int col = nt * 8 + qcol;
                if (d0 >= 0) red_add_v2(o0 + col, c[0] * nm0, c[1] * nm0);
                if (d1 >= 0) red_add_v2(o1 + col, c[2] * nm1, c[3] * nm1);
            }
        }
    }
    #undef A_ISSUE
    #undef COMPUTE
}

// ---------------------------------------------------------------------------
// K7: finalize  out = (deg>0 ? out/deg : 0) + bias
// ---------------------------------------------------------------------------
__global__ __launch_bounds__(256)
void finalize_kernel(const float* __restrict__ bias, float4* __restrict__ out) {
    size_t idx = (size_t)blockIdx.x * blockDim.x + threadIdx.x;
    const size_t tot4 = (size_t)NNODES * DIM / 4;
    if (idx >= tot4) return;
    int n  = (int)(idx >> 6);
    int d4 = (int)(idx & 63);
    int cnt = g_dcnt[n];
    float inv = (cnt > 0) ? (1.0f / (float)cnt) : 0.0f;
    float4 v = out[idx];
    float4 bb = ((const float4*)bias)[d4];
    v.x = fmaf(v.x, inv, bb.x);
    v.y = fmaf(v.y, inv, bb.y);
    v.z = fmaf(v.z, inv, bb.z);
    v.w = fmaf(v.w, inv, bb.w);
    out[idx] = v;
}

// ---------------------------------------------------------------------------
// kernel_launch
// Inputs (metadata order): node_ids[i32,N], src[i32,E], dst[i32,E],
//   etypes[i32,E], norm[f32,E], emb[f32,N*D], basis[f32,B*D*D],
//   w_comp[f32,R*B], h_bias[f32,D].  Output: f32 [N, D].
// ---------------------------------------------------------------------------
extern "C" void kernel_launch(void* const* d_in, const int* in_sizes, int n_in,
                              void* d_out, int out_size) {
    const int*   node_ids = (const int*)  d_in[0];
    const int*   src      = (const int*)  d_in[1];
    const int*   dst      = (const int*)  d_in[2];
    const int*   etypes   = (const int*)  d_in[3];
    const float* norm     = (const float*)d_in[4];
    const float* emb      = (const float*)d_in[5];
    const float* basis    = (const float*)d_in[6];
    const float* w_comp   = (const float*)d_in[7];
    const float* h_bias   = (const float*)d_in[8];
    float* out = (float*)d_out;

    const int tot4 = NNODES * DIM / 4;
    const int blk4 = (tot4 + 255) / 256;

    cudaFuncSetAttribute(gemm_persist_kernel,
                         cudaFuncAttributeMaxDynamicSharedMemorySize, SM_TOTAL);

    prep_kernel<<<blk4, 256>>>(emb, node_ids, (float4*)out);
    build_w_kernel<<<(DIM * DIM + 255) / 256, 256>>>(basis, w_comp);

    ehist_kernel<<<(NEDGES + 255) / 256, 256>>>(etypes, dst);
    scan16_kernel<<<1, 32>>>();
    fill_kernel<<<(NEDGES + 255) / 256, 256>>>(etypes);

    gemm_persist_kernel<<<NCTA_PERSIST, 256, SM_TOTAL>>>(src, dst, norm, out);

    finalize_kernel<<<blk4, 256>>>(h_bias, (float4*)out);
}